// round 2
// baseline (speedup 1.0000x reference)
#include <cuda_runtime.h>
#include <math.h>
#include <stdint.h>

#define EMBED 768
#define HEADS 12
#define HDIM  64
#define FF    1536
#define BATCH 4
#define LQ    2048
#define LK    2048
#define MQ    (BATCH*LQ)   /* 8192 */
#define MK    (BATCH*LK)   /* 8192 */

// ---------------- scratch (no allocations allowed) ----------------
__device__ float g_tmpA[MQ*EMBED];
__device__ float g_tmpB[MK*EMBED];
__device__ float g_q  [MQ*EMBED];
__device__ float g_k  [MK*EMBED];
__device__ float g_v  [MK*EMBED];
__device__ float g_att[MQ*EMBED];
__device__ float g_ln1[MQ*EMBED];
__device__ float g_ff [MQ*FF];

// ---------------- SGEMM 128x128x8, fp32, C = A@W + bias (+R | gelu) ----------------
// EPI: 0 = bias only, 1 = bias + residual R, 2 = bias then exact GELU
template<int EPI>
__global__ __launch_bounds__(256, 2)
void sgemm128(const float* __restrict__ A, const float* __restrict__ W,
              const float* __restrict__ bias, const float* __restrict__ R,
              float* __restrict__ C, int M, int N, int K)
{
    __shared__ float As[8][132];   // transposed A tile, padded (528B rows, 16B aligned)
    __shared__ float Bs[8][128];

    const int bm  = blockIdx.y * 128;
    const int bn  = blockIdx.x * 128;
    const int tid = threadIdx.x;
    const int tx  = tid & 15;
    const int ty  = tid >> 4;

    const int arow = tid >> 1;
    const int acol = (tid & 1) << 2;
    const int brow = tid >> 5;
    const int bcol = (tid & 31) << 2;

    const float* Ab = A + (size_t)(bm + arow) * K + acol;
    const float* Wb = W + (size_t)brow * N + bn + bcol;

    float acc[8][8];
    #pragma unroll
    for (int i = 0; i < 8; i++)
        #pragma unroll
        for (int j = 0; j < 8; j++) acc[i][j] = 0.f;

    for (int k0 = 0; k0 < K; k0 += 8) {
        float4 av = *(const float4*)(Ab + k0);
        float4 bv = *(const float4*)(Wb + (size_t)k0 * N);
        As[acol+0][arow] = av.x;
        As[acol+1][arow] = av.y;
        As[acol+2][arow] = av.z;
        As[acol+3][arow] = av.w;
        *(float4*)(&Bs[brow][bcol]) = bv;
        __syncthreads();
        #pragma unroll
        for (int kk = 0; kk < 8; kk++) {
            float a[8], b[8];
            *(float4*)(a)   = *(const float4*)(&As[kk][ty*8]);
            *(float4*)(a+4) = *(const float4*)(&As[kk][ty*8+4]);
            *(float4*)(b)   = *(const float4*)(&Bs[kk][tx*8]);
            *(float4*)(b+4) = *(const float4*)(&Bs[kk][tx*8+4]);
            #pragma unroll
            for (int i = 0; i < 8; i++)
                #pragma unroll
                for (int j = 0; j < 8; j++)
                    acc[i][j] = fmaf(a[i], b[j], acc[i][j]);
        }
        __syncthreads();
    }

    #pragma unroll
    for (int i = 0; i < 8; i++) {
        const int row = bm + ty*8 + i;
        #pragma unroll
        for (int j = 0; j < 8; j++) {
            const int col = bn + tx*8 + j;
            float v = acc[i][j] + bias[col];
            if (EPI == 1) v += R[(size_t)row * N + col];
            if (EPI == 2) v = 0.5f * v * (1.f + erff(v * 0.70710678118654752f));
            C[(size_t)row * N + col] = v;
        }
    }
}

// ---------------- per-head L2 normalize (64-dim vectors), in place ----------------
__global__ void l2norm_kernel(float* __restrict__ x, int nvec)
{
    const int warp = (blockIdx.x * blockDim.x + threadIdx.x) >> 5;
    const int lane = threadIdx.x & 31;
    if (warp >= nvec) return;
    float* p = x + (size_t)warp * HDIM;
    float a = p[lane], b = p[lane + 32];
    float ss = a*a + b*b;
    #pragma unroll
    for (int m = 16; m; m >>= 1) ss += __shfl_xor_sync(0xffffffffu, ss, m);
    float n   = sqrtf(ss);
    float inv = 1.f / fmaxf(n, 1e-12f);
    p[lane]      = a * inv;
    p[lane + 32] = b * inv;
}

// ---------------- LayerNorm over 768, two-pass for accuracy ----------------
__global__ void layernorm_kernel(const float* __restrict__ x,
                                 const float* __restrict__ g,
                                 const float* __restrict__ b,
                                 float* __restrict__ y)
{
    const int row = blockIdx.x;
    const float* xr = x + (size_t)row * EMBED;
    float* yr       = y + (size_t)row * EMBED;
    const int tid = threadIdx.x;   // 256 threads, 3 elems each

    float v0 = xr[tid], v1 = xr[tid + 256], v2 = xr[tid + 512];

    __shared__ float red[8];
    float s = v0 + v1 + v2;
    #pragma unroll
    for (int m = 16; m; m >>= 1) s += __shfl_xor_sync(0xffffffffu, s, m);
    if ((tid & 31) == 0) red[tid >> 5] = s;
    __syncthreads();
    s = 0.f;
    #pragma unroll
    for (int w = 0; w < 8; w++) s += red[w];
    const float mu = s * (1.f / EMBED);
    __syncthreads();

    float d0 = v0 - mu, d1 = v1 - mu, d2 = v2 - mu;
    float ss = d0*d0 + d1*d1 + d2*d2;
    #pragma unroll
    for (int m = 16; m; m >>= 1) ss += __shfl_xor_sync(0xffffffffu, ss, m);
    if ((tid & 31) == 0) red[tid >> 5] = ss;
    __syncthreads();
    ss = 0.f;
    #pragma unroll
    for (int w = 0; w < 8; w++) ss += red[w];
    const float inv = rsqrtf(ss * (1.f / EMBED) + 1e-5f);

    yr[tid]       = d0 * inv * g[tid]       + b[tid];
    yr[tid + 256] = d1 * inv * g[tid + 256] + b[tid + 256];
    yr[tid + 512] = d2 * inv * g[tid + 512] + b[tid + 512];
}

// ---------------- flash attention: 64-row q tiles, 64-row k/v tiles ----------------
// q,k already L2-normalized; scores = q.k (no scale). Output written in [B,Lq,E] layout.
#define ATT_SMEM (4 * 64 * 65 * 4)

__global__ __launch_bounds__(256)
void flash_attn_kernel(const float* __restrict__ q, const float* __restrict__ k,
                       const float* __restrict__ v, float* __restrict__ out)
{
    extern __shared__ float sm[];
    float* qT = sm;             // qT[d*65 + r]
    float* kT = sm + 64*65;     // kT[d*65 + c]
    float* Vs = sm + 2*64*65;   // Vs[j*65 + c]
    float* PT = sm + 3*64*65;   // PT[c*65 + r]
    __shared__ float row_m[64], row_l[64], row_scale[64];

    const int tid = threadIdx.x;
    const int tx = tid & 15, ty = tid >> 4;
    const int r0 = ty * 4, c0 = tx * 4;
    const int q0 = blockIdx.x * 64;
    const int h  = blockIdx.y;
    const int b  = blockIdx.z;

    const float* qb = q + ((size_t)(b*LQ + q0)) * EMBED + h * HDIM;
    const float* kb = k + ((size_t)(b*LK))      * EMBED + h * HDIM;
    const float* vb = v + ((size_t)(b*LK))      * EMBED + h * HDIM;

    for (int idx = tid; idx < 64*64; idx += 256) {
        int r = idx >> 6, d = idx & 63;
        qT[d*65 + r] = qb[(size_t)r * EMBED + d];
    }
    if (tid < 64) { row_m[tid] = -1e30f; row_l[tid] = 0.f; }

    float o[4][4];
    #pragma unroll
    for (int i = 0; i < 4; i++)
        #pragma unroll
        for (int j = 0; j < 4; j++) o[i][j] = 0.f;

    for (int kt = 0; kt < LK/64; kt++) {
        __syncthreads();
        const float* kp = kb + (size_t)kt * 64 * EMBED;
        const float* vp = vb + (size_t)kt * 64 * EMBED;
        for (int idx = tid; idx < 64*64; idx += 256) {
            int r = idx >> 6, d = idx & 63;
            kT[d*65 + r] = kp[(size_t)r * EMBED + d];
            Vs[r*65 + d] = vp[(size_t)r * EMBED + d];
        }
        __syncthreads();

        // S = q @ k^T for this block's 4x4 patch
        float s[4][4];
        #pragma unroll
        for (int i = 0; i < 4; i++)
            #pragma unroll
            for (int j = 0; j < 4; j++) s[i][j] = 0.f;

        #pragma unroll 4
        for (int d = 0; d < 64; d++) {
            float a0 = qT[d*65 + r0+0], a1 = qT[d*65 + r0+1];
            float a2 = qT[d*65 + r0+2], a3 = qT[d*65 + r0+3];
            float b0 = kT[d*65 + c0+0], b1 = kT[d*65 + c0+1];
            float b2 = kT[d*65 + c0+2], b3 = kT[d*65 + c0+3];
            s[0][0]=fmaf(a0,b0,s[0][0]); s[0][1]=fmaf(a0,b1,s[0][1]);
            s[0][2]=fmaf(a0,b2,s[0][2]); s[0][3]=fmaf(a0,b3,s[0][3]);
            s[1][0]=fmaf(a1,b0,s[1][0]); s[1][1]=fmaf(a1,b1,s[1][1]);
            s[1][2]=fmaf(a1,b2,s[1][2]); s[1][3]=fmaf(a1,b3,s[1][3]);
            s[2][0]=fmaf(a2,b0,s[2][0]); s[2][1]=fmaf(a2,b1,s[2][1]);
            s[2][2]=fmaf(a2,b2,s[2][2]); s[2][3]=fmaf(a2,b3,s[2][3]);
            s[3][0]=fmaf(a3,b0,s[3][0]); s[3][1]=fmaf(a3,b1,s[3][1]);
            s[3][2]=fmaf(a3,b2,s[3][2]); s[3][3]=fmaf(a3,b3,s[3][3]);
        }
        #pragma unroll
        for (int j = 0; j < 4; j++)
            #pragma unroll
            for (int i = 0; i < 4; i++)
                PT[(c0+j)*65 + r0+i] = s[i][j];
        __syncthreads();

        // online softmax: 4 threads per row, 16 cols each
        {
            const int r = tid >> 2, part = tid & 3;
            const int jb = part * 16;
            float mx = -1e30f;
            #pragma unroll
            for (int j = 0; j < 16; j++) mx = fmaxf(mx, PT[(jb+j)*65 + r]);
            mx = fmaxf(mx, __shfl_xor_sync(0xffffffffu, mx, 1));
            mx = fmaxf(mx, __shfl_xor_sync(0xffffffffu, mx, 2));
            const float m_old = row_m[r];
            const float m_new = fmaxf(m_old, mx);
            float sum = 0.f;
            #pragma unroll
            for (int j = 0; j < 16; j++) {
                float p = __expf(PT[(jb+j)*65 + r] - m_new);
                PT[(jb+j)*65 + r] = p;
                sum += p;
            }
            sum += __shfl_xor_sync(0xffffffffu, sum, 1);
            sum += __shfl_xor_sync(0xffffffffu, sum, 2);
            if (part == 0) {
                float sc = __expf(m_old - m_new);
                row_scale[r] = sc;
                row_m[r]     = m_new;
                row_l[r]     = row_l[r] * sc + sum;
            }
        }
        __syncthreads();

        // rescale accumulators then O += P @ V
        float sc0 = row_scale[r0+0], sc1 = row_scale[r0+1];
        float sc2 = row_scale[r0+2], sc3 = row_scale[r0+3];
        #pragma unroll
        for (int j = 0; j < 4; j++) {
            o[0][j] *= sc0; o[1][j] *= sc1; o[2][j] *= sc2; o[3][j] *= sc3;
        }
        #pragma unroll 4
        for (int j = 0; j < 64; j++) {
            float p0 = PT[j*65 + r0+0], p1 = PT[j*65 + r0+1];
            float p2 = PT[j*65 + r0+2], p3 = PT[j*65 + r0+3];
            float w0 = Vs[j*65 + c0+0], w1 = Vs[j*65 + c0+1];
            float w2 = Vs[j*65 + c0+2], w3 = Vs[j*65 + c0+3];
            o[0][0]=fmaf(p0,w0,o[0][0]); o[0][1]=fmaf(p0,w1,o[0][1]);
            o[0][2]=fmaf(p0,w2,o[0][2]); o[0][3]=fmaf(p0,w3,o[0][3]);
            o[1][0]=fmaf(p1,w0,o[1][0]); o[1][1]=fmaf(p1,w1,o[1][1]);
            o[1][2]=fmaf(p1,w2,o[1][2]); o[1][3]=fmaf(p1,w3,o[1][3]);
            o[2][0]=fmaf(p2,w0,o[2][0]); o[2][1]=fmaf(p2,w1,o[2][1]);
            o[2][2]=fmaf(p2,w2,o[2][2]); o[2][3]=fmaf(p2,w3,o[2][3]);
            o[3][0]=fmaf(p3,w0,o[3][0]); o[3][1]=fmaf(p3,w1,o[3][1]);
            o[3][2]=fmaf(p3,w2,o[3][2]); o[3][3]=fmaf(p3,w3,o[3][3]);
        }
    }

    #pragma unroll
    for (int i = 0; i < 4; i++) {
        const float inv = 1.f / row_l[r0 + i];
        float4 vo = make_float4(o[i][0]*inv, o[i][1]*inv, o[i][2]*inv, o[i][3]*inv);
        *(float4*)&out[((size_t)(b*LQ + q0 + r0 + i)) * EMBED + h*HDIM + c0] = vo;
    }
}

// ---------------- launch ----------------
extern "C" void kernel_launch(void* const* d_in, const int* in_sizes, int n_in,
                              void* d_out, int out_size)
{
    const float* image_tokens = (const float*)d_in[0];
    const float* point_tokens = (const float*)d_in[1];
    const float* image_pos    = (const float*)d_in[2];
    const float* point_pos    = (const float*)d_in[3];
    const float* Wip = (const float*)d_in[4];   const float* bip = (const float*)d_in[5];
    const float* Wpp = (const float*)d_in[6];   const float* bpp = (const float*)d_in[7];
    const float* Wq  = (const float*)d_in[8];   const float* bq  = (const float*)d_in[9];
    const float* Wk  = (const float*)d_in[10];  const float* bk  = (const float*)d_in[11];
    const float* Wv  = (const float*)d_in[12];  const float* bv  = (const float*)d_in[13];
    const float* Wo  = (const float*)d_in[14];  const float* bo  = (const float*)d_in[15];
    const float* g1  = (const float*)d_in[16];  const float* b1  = (const float*)d_in[17];
    const float* g2  = (const float*)d_in[18];  const float* b2  = (const float*)d_in[19];
    const float* Wf1 = (const float*)d_in[20];  const float* bf1 = (const float*)d_in[21];
    const float* Wf2 = (const float*)d_in[22];  const float* bf2 = (const float*)d_in[23];
    float* out = (float*)d_out;

    float *tmpA, *tmpB, *qp, *kp, *vp, *attp, *ln1p, *ffp;
    cudaGetSymbolAddress((void**)&tmpA, g_tmpA);
    cudaGetSymbolAddress((void**)&tmpB, g_tmpB);
    cudaGetSymbolAddress((void**)&qp,   g_q);
    cudaGetSymbolAddress((void**)&kp,   g_k);
    cudaGetSymbolAddress((void**)&vp,   g_v);
    cudaGetSymbolAddress((void**)&attp, g_att);
    cudaGetSymbolAddress((void**)&ln1p, g_ln1);
    cudaGetSymbolAddress((void**)&ffp,  g_ff);

    const dim3 blk(256);

    // q/k input projections with positional-embedding linears + residual
    sgemm128<1><<<dim3(EMBED/128, MQ/128), blk>>>(image_pos, Wip, bip, image_tokens, tmpA, MQ, EMBED, EMBED);
    sgemm128<1><<<dim3(EMBED/128, MK/128), blk>>>(point_pos, Wpp, bpp, point_tokens, tmpB, MK, EMBED, EMBED);
    // q, k, v projections
    sgemm128<0><<<dim3(EMBED/128, MQ/128), blk>>>(tmpA, Wq, bq, nullptr, qp, MQ, EMBED, EMBED);
    sgemm128<0><<<dim3(EMBED/128, MK/128), blk>>>(tmpB, Wk, bk, nullptr, kp, MK, EMBED, EMBED);
    sgemm128<0><<<dim3(EMBED/128, MK/128), blk>>>(point_tokens, Wv, bv, nullptr, vp, MK, EMBED, EMBED);
    // per-head L2 normalization of q, k
    l2norm_kernel<<<(MQ*HEADS)/8, 256>>>(qp, MQ*HEADS);
    l2norm_kernel<<<(MK*HEADS)/8, 256>>>(kp, MK*HEADS);
    // attention
    cudaFuncSetAttribute(flash_attn_kernel, cudaFuncAttributeMaxDynamicSharedMemorySize, ATT_SMEM);
    flash_attn_kernel<<<dim3(LQ/64, HEADS, BATCH), 256, ATT_SMEM>>>(qp, kp, vp, attp);
    // output projection + residual, then LN1
    sgemm128<1><<<dim3(EMBED/128, MQ/128), blk>>>(attp, Wo, bo, image_tokens, tmpA, MQ, EMBED, EMBED);
    layernorm_kernel<<<MQ, 256>>>(tmpA, g1, b1, ln1p);
    // FFN: GELU(ln1 @ Wf1 + bf1) @ Wf2 + bf2 + ln1, then LN2 -> out
    sgemm128<2><<<dim3(FF/128, MQ/128), blk>>>(ln1p, Wf1, bf1, nullptr, ffp, MQ, FF, EMBED);
    sgemm128<1><<<dim3(EMBED/128, MQ/128), blk>>>(ffp, Wf2, bf2, ln1p, tmpA, MQ, EMBED, FF);
    layernorm_kernel<<<MQ, 256>>>(tmpA, g2, b2, out);
}

// round 3
// speedup vs baseline: 3.7520x; 3.7520x over previous
#include <cuda_runtime.h>
#include <math.h>
#include <stdint.h>

#define EMBED 768
#define HEADS 12
#define HDIM  64
#define FF    1536
#define BATCH 4
#define LQ    2048
#define LK    2048
#define MQ    (BATCH*LQ)   /* 8192 */
#define MK    (BATCH*LK)   /* 8192 */

// ---------------- scratch (no allocations allowed) ----------------
__device__ float g_tmpA[MQ*EMBED];
__device__ float g_tmpB[MK*EMBED];
__device__ float g_q  [MQ*EMBED];
__device__ float g_k  [MK*EMBED];
__device__ float g_v  [MK*EMBED];
__device__ float g_att[MQ*EMBED];
__device__ float g_ln1[MQ*EMBED];
__device__ float g_ff [MQ*FF];
// tf32-rounded weights: Wip,Wpp,Wq,Wk,Wv,Wo (768x768 each), Wf1, Wf2 (768x1536)
#define WSZ   (EMBED*EMBED)
#define WFSZ  (EMBED*FF)
__device__ float g_wr [6*WSZ + 2*WFSZ];

// ---------------- helpers ----------------
__device__ __forceinline__ uint32_t f2tf(float x) {
    uint32_t u; asm("cvt.rna.tf32.f32 %0, %1;" : "=r"(u) : "f"(x)); return u;
}
__device__ __forceinline__ float ftf32(float x) {
    uint32_t u; asm("cvt.rna.tf32.f32 %0, %1;" : "=r"(u) : "f"(x)); return __uint_as_float(u);
}
__device__ __forceinline__ void cpasync16(void* s, const void* g) {
    uint32_t sa = (uint32_t)__cvta_generic_to_shared(s);
    asm volatile("cp.async.cg.shared.global [%0], [%1], 16;" :: "r"(sa), "l"(g));
}
#define CP_COMMIT() asm volatile("cp.async.commit_group;")
#define CP_WAIT0()  asm volatile("cp.async.wait_group 0;")

__device__ __forceinline__ void mma_tf32(float c[4],
    uint32_t a0, uint32_t a1, uint32_t a2, uint32_t a3, uint32_t b0, uint32_t b1)
{
    asm volatile(
        "mma.sync.aligned.m16n8k8.row.col.f32.tf32.tf32.f32 "
        "{%0,%1,%2,%3}, {%4,%5,%6,%7}, {%8,%9}, {%0,%1,%2,%3};"
        : "+f"(c[0]), "+f"(c[1]), "+f"(c[2]), "+f"(c[3])
        : "r"(a0), "r"(a1), "r"(a2), "r"(a3), "r"(b0), "r"(b1));
}

// ---------------- weight rounding ----------------
__global__ void roundw_kernel(const float* __restrict__ s, float* __restrict__ d, int n)
{
    int i = blockIdx.x * 256 + threadIdx.x;
    if (i < n) d[i] = ftf32(s[i]);
}

// ---------------- tf32 GEMM 128x128x32, C = A @ W + bias (+R | gelu | round) ----------------
// EPI bit0 = +residual R, bit1 = exact GELU, bit2 = round output to tf32
#define GEMM_SMEM ((2*128*36 + 2*32*136) * 4)

template<int EPI>
__global__ __launch_bounds__(256, 2)
void tf32gemm(const float* __restrict__ A, const float* __restrict__ W,
              const float* __restrict__ bias, const float* __restrict__ R,
              float* __restrict__ C, int M, int N, int K)
{
    extern __shared__ float sm[];
    float* As0 = sm;
    float* As1 = sm + 128*36;
    float* Bs0 = sm + 2*128*36;
    float* Bs1 = sm + 2*128*36 + 32*136;

    const int tid  = threadIdx.x;
    const int lane = tid & 31;
    const int warp = tid >> 5;
    const int wm   = warp & 3;          // 4 warps along M
    const int wn   = warp >> 2;         // 2 warps along N
    const int bm   = blockIdx.y * 128;
    const int bn   = blockIdx.x * 128;

    const int arow = tid >> 3;          // 0..31 (+32p)
    const int acol = (tid & 7) * 4;     // 0..28
    const int bk   = tid >> 5;          // 0..7 (+8p)
    const int bcol = (tid & 31) * 4;    // 0..124

    const int NT = K / 32;

    float acc[2][8][4];
    #pragma unroll
    for (int mi = 0; mi < 2; mi++)
        #pragma unroll
        for (int ni = 0; ni < 8; ni++)
            #pragma unroll
            for (int t = 0; t < 4; t++) acc[mi][ni][t] = 0.f;

    // prefetch stage 0
    {
        const float* Ag = A + (size_t)bm * K;
        const float* Wg = W;
        #pragma unroll
        for (int p = 0; p < 4; p++) {
            int r = arow + 32*p;
            cpasync16(&As0[r*36 + acol], Ag + (size_t)r * K + acol);
        }
        #pragma unroll
        for (int p = 0; p < 4; p++) {
            int kk = bk + 8*p;
            cpasync16(&Bs0[kk*136 + bcol], Wg + (size_t)kk * N + bn + bcol);
        }
        CP_COMMIT();
    }

    for (int kt = 0; kt < NT; kt++) {
        CP_WAIT0();
        __syncthreads();

        float* as = (kt & 1) ? As1 : As0;
        float* bs = (kt & 1) ? Bs1 : Bs0;

        if (kt + 1 < NT) {
            float* asn = (kt & 1) ? As0 : As1;
            float* bsn = (kt & 1) ? Bs0 : Bs1;
            const float* Ag = A + (size_t)bm * K + (kt+1)*32;
            const float* Wg = W + (size_t)(kt+1)*32 * N;
            #pragma unroll
            for (int p = 0; p < 4; p++) {
                int r = arow + 32*p;
                cpasync16(&asn[r*36 + acol], Ag + (size_t)r * K + acol);
            }
            #pragma unroll
            for (int p = 0; p < 4; p++) {
                int kk = bk + 8*p;
                cpasync16(&bsn[kk*136 + bcol], Wg + (size_t)kk * N + bn + bcol);
            }
            CP_COMMIT();
        }

        #pragma unroll
        for (int kk = 0; kk < 4; kk++) {
            const int kb = kk * 8;
            uint32_t af[2][4];
            #pragma unroll
            for (int mi = 0; mi < 2; mi++) {
                const float* ap = as + (wm*32 + mi*16 + (lane>>2))*36 + kb + (lane & 3);
                af[mi][0] = f2tf(ap[0]);
                af[mi][1] = f2tf(ap[8*36]);
                af[mi][2] = f2tf(ap[4]);
                af[mi][3] = f2tf(ap[8*36 + 4]);
            }
            uint32_t bf[8][2];
            #pragma unroll
            for (int ni = 0; ni < 8; ni++) {
                const float* bp = bs + (kb + (lane & 3))*136 + wn*64 + ni*8 + (lane>>2);
                bf[ni][0] = __float_as_uint(bp[0]);      // weights pre-rounded
                bf[ni][1] = __float_as_uint(bp[4*136]);
            }
            #pragma unroll
            for (int mi = 0; mi < 2; mi++)
                #pragma unroll
                for (int ni = 0; ni < 8; ni++)
                    mma_tf32(acc[mi][ni], af[mi][0], af[mi][1], af[mi][2], af[mi][3],
                             bf[ni][0], bf[ni][1]);
        }
    }

    // epilogue
    #pragma unroll
    for (int mi = 0; mi < 2; mi++) {
        const int r0 = bm + wm*32 + mi*16 + (lane>>2);
        #pragma unroll
        for (int ni = 0; ni < 8; ni++) {
            const int c = bn + wn*64 + ni*8 + 2*(lane & 3);
            const float2 bb = *(const float2*)(bias + c);
            #pragma unroll
            for (int half = 0; half < 2; half++) {
                const int r = r0 + half*8;
                float v0 = acc[mi][ni][2*half+0] + bb.x;
                float v1 = acc[mi][ni][2*half+1] + bb.y;
                if (EPI & 1) {
                    const float2 rr = *(const float2*)(R + (size_t)r * N + c);
                    v0 += rr.x; v1 += rr.y;
                }
                if (EPI & 2) {
                    v0 = 0.5f * v0 * (1.f + erff(v0 * 0.70710678118654752f));
                    v1 = 0.5f * v1 * (1.f + erff(v1 * 0.70710678118654752f));
                }
                if (EPI & 4) { v0 = ftf32(v0); v1 = ftf32(v1); }
                *(float2*)(C + (size_t)r * N + c) = make_float2(v0, v1);
            }
        }
    }
}

// ---------------- per-head L2 normalize + tf32 round, in place ----------------
__global__ void l2norm_kernel(float* __restrict__ x, int nvec)
{
    const int warp = (blockIdx.x * blockDim.x + threadIdx.x) >> 5;
    const int lane = threadIdx.x & 31;
    if (warp >= nvec) return;
    float* p = x + (size_t)warp * HDIM;
    float a = p[lane], b = p[lane + 32];
    float ss = a*a + b*b;
    #pragma unroll
    for (int m = 16; m; m >>= 1) ss += __shfl_xor_sync(0xffffffffu, ss, m);
    float n   = sqrtf(ss);
    float inv = 1.f / fmaxf(n, 1e-12f);
    p[lane]      = ftf32(a * inv);
    p[lane + 32] = ftf32(b * inv);
}

// ---------------- LayerNorm over 768 ----------------
__global__ void layernorm_kernel(const float* __restrict__ x,
                                 const float* __restrict__ g,
                                 const float* __restrict__ b,
                                 float* __restrict__ y)
{
    const int row = blockIdx.x;
    const float* xr = x + (size_t)row * EMBED;
    float* yr       = y + (size_t)row * EMBED;
    const int tid = threadIdx.x;

    float v0 = xr[tid], v1 = xr[tid + 256], v2 = xr[tid + 512];

    __shared__ float red[8];
    float s = v0 + v1 + v2;
    #pragma unroll
    for (int m = 16; m; m >>= 1) s += __shfl_xor_sync(0xffffffffu, s, m);
    if ((tid & 31) == 0) red[tid >> 5] = s;
    __syncthreads();
    s = 0.f;
    #pragma unroll
    for (int w = 0; w < 8; w++) s += red[w];
    const float mu = s * (1.f / EMBED);
    __syncthreads();

    float d0 = v0 - mu, d1 = v1 - mu, d2 = v2 - mu;
    float ss = d0*d0 + d1*d1 + d2*d2;
    #pragma unroll
    for (int m = 16; m; m >>= 1) ss += __shfl_xor_sync(0xffffffffu, ss, m);
    if ((tid & 31) == 0) red[tid >> 5] = ss;
    __syncthreads();
    ss = 0.f;
    #pragma unroll
    for (int w = 0; w < 8; w++) ss += red[w];
    const float inv = rsqrtf(ss * (1.f / EMBED) + 1e-5f);

    yr[tid]       = d0 * inv * g[tid]       + b[tid];
    yr[tid + 256] = d1 * inv * g[tid + 256] + b[tid + 256];
    yr[tid + 512] = d2 * inv * g[tid + 512] + b[tid + 512];
}

// ---------------- tensor-core flash attention ----------------
// q,k unit vectors => scores in [-1,1] => fixed-max softmax: p = exp(s-1), no online max.
// 128 threads / 4 warps; q-tile 64 (16 rows/warp); kv-tile 64, double-buffered.
#define ATT_SMEM ((64*68 + 2*64*68 + 2*64*72 + 64*68) * 4)

__global__ __launch_bounds__(128)
void attn_kernel(const float* __restrict__ q, const float* __restrict__ k,
                 const float* __restrict__ v, float* __restrict__ out)
{
    extern __shared__ float sm[];
    float* Qs  = sm;                        // [64][68]
    float* Ks0 = Qs  + 64*68;               // [64][68] x2
    float* Ks1 = Ks0 + 64*68;
    float* Vs0 = Ks1 + 64*68;               // [64][72] x2
    float* Vs1 = Vs0 + 64*72;
    float* Ps  = Vs1 + 64*72;               // [4 warps][16][68]

    const int tid  = threadIdx.x;
    const int lane = tid & 31;
    const int warp = tid >> 5;
    const int q0 = blockIdx.x * 64;
    const int h  = blockIdx.y;
    const int b  = blockIdx.z;

    const float* qb = q + ((size_t)(b*LQ + q0)) * EMBED + h * HDIM;
    const float* kb = k + ((size_t)(b*LK))      * EMBED + h * HDIM;
    const float* vb = v + ((size_t)(b*LK))      * EMBED + h * HDIM;

    // load Q tile + first K/V tiles
    #pragma unroll
    for (int p = 0; p < 8; p++) {
        int idx = tid + 128*p;
        int r = idx >> 4, c = (idx & 15) * 4;
        cpasync16(&Qs[r*68 + c], qb + (size_t)r * EMBED + c);
    }
    #pragma unroll
    for (int p = 0; p < 8; p++) {
        int idx = tid + 128*p;
        int r = idx >> 4, c = (idx & 15) * 4;
        cpasync16(&Ks0[r*68 + c], kb + (size_t)r * EMBED + c);
        cpasync16(&Vs0[r*72 + c], vb + (size_t)r * EMBED + c);
    }
    CP_COMMIT();

    float o[8][4];
    #pragma unroll
    for (int ni = 0; ni < 8; ni++)
        #pragma unroll
        for (int t = 0; t < 4; t++) o[ni][t] = 0.f;
    float l0 = 0.f, l1 = 0.f;

    float* Pw = Ps + warp*16*68;
    const int rql = (lane >> 2);            // warp-local row group 0..7

    for (int kt = 0; kt < LK/64; kt++) {
        CP_WAIT0();
        __syncthreads();

        float* ks = (kt & 1) ? Ks1 : Ks0;
        float* vs = (kt & 1) ? Vs1 : Vs0;

        if (kt + 1 < LK/64) {
            float* ksn = (kt & 1) ? Ks0 : Ks1;
            float* vsn = (kt & 1) ? Vs0 : Vs1;
            const float* kp = kb + (size_t)(kt+1) * 64 * EMBED;
            const float* vp = vb + (size_t)(kt+1) * 64 * EMBED;
            #pragma unroll
            for (int p = 0; p < 8; p++) {
                int idx = tid + 128*p;
                int r = idx >> 4, c = (idx & 15) * 4;
                cpasync16(&ksn[r*68 + c], kp + (size_t)r * EMBED + c);
                cpasync16(&vsn[r*72 + c], vp + (size_t)r * EMBED + c);
            }
            CP_COMMIT();
        }

        // S = Q @ K^T   (warp: 16 rows x 64 keys)
        float s[8][4];
        #pragma unroll
        for (int ni = 0; ni < 8; ni++)
            #pragma unroll
            for (int t = 0; t < 4; t++) s[ni][t] = 0.f;

        #pragma unroll
        for (int kk = 0; kk < 8; kk++) {
            const int kbs = kk * 8;
            const float* ap = Qs + (warp*16 + rql)*68 + kbs + (lane & 3);
            uint32_t a0 = __float_as_uint(ap[0]);        // Q pre-rounded tf32
            uint32_t a1 = __float_as_uint(ap[8*68]);
            uint32_t a2 = __float_as_uint(ap[4]);
            uint32_t a3 = __float_as_uint(ap[8*68 + 4]);
            #pragma unroll
            for (int ni = 0; ni < 8; ni++) {
                const float* bp = ks + (ni*8 + rql)*68 + kbs + (lane & 3);
                mma_tf32(s[ni], a0, a1, a2, a3,
                         __float_as_uint(bp[0]), __float_as_uint(bp[4]));
            }
        }

        // p = exp(s - 1); accumulate row sums; store rounded P
        #pragma unroll
        for (int ni = 0; ni < 8; ni++) {
            float p0 = ftf32(__expf(s[ni][0] - 1.f));
            float p1 = ftf32(__expf(s[ni][1] - 1.f));
            float p2 = ftf32(__expf(s[ni][2] - 1.f));
            float p3 = ftf32(__expf(s[ni][3] - 1.f));
            l0 += p0 + p1;
            l1 += p2 + p3;
            float* pp = Pw + rql*68 + ni*8 + 2*(lane & 3);
            *(float2*)pp            = make_float2(p0, p1);
            *(float2*)(pp + 8*68)   = make_float2(p2, p3);
        }
        __syncwarp();

        // O += P @ V   (k = 64 keys, n = 64 dims)
        #pragma unroll
        for (int kk = 0; kk < 8; kk++) {
            const int kbs = kk * 8;
            const float* ap = Pw + rql*68 + kbs + (lane & 3);
            uint32_t a0 = __float_as_uint(ap[0]);
            uint32_t a1 = __float_as_uint(ap[8*68]);
            uint32_t a2 = __float_as_uint(ap[4]);
            uint32_t a3 = __float_as_uint(ap[8*68 + 4]);
            #pragma unroll
            for (int ni = 0; ni < 8; ni++) {
                const float* bp = vs + (kbs + (lane & 3))*72 + ni*8 + rql;
                mma_tf32(o[ni], a0, a1, a2, a3,
                         __float_as_uint(bp[0]), __float_as_uint(bp[4*72]));
            }
        }
    }

    // finalize: reduce row sums across quad, normalize, store
    l0 += __shfl_xor_sync(0xffffffffu, l0, 1);
    l0 += __shfl_xor_sync(0xffffffffu, l0, 2);
    l1 += __shfl_xor_sync(0xffffffffu, l1, 1);
    l1 += __shfl_xor_sync(0xffffffffu, l1, 2);
    const float inv0 = 1.f / l0, inv1 = 1.f / l1;

    const int r = b*LQ + q0 + warp*16 + rql;
    #pragma unroll
    for (int ni = 0; ni < 8; ni++) {
        const int c = h*HDIM + ni*8 + 2*(lane & 3);
        *(float2*)(out + (size_t)r * EMBED + c)       = make_float2(o[ni][0]*inv0, o[ni][1]*inv0);
        *(float2*)(out + (size_t)(r+8) * EMBED + c)   = make_float2(o[ni][2]*inv1, o[ni][3]*inv1);
    }
}

// ---------------- launch ----------------
extern "C" void kernel_launch(void* const* d_in, const int* in_sizes, int n_in,
                              void* d_out, int out_size)
{
    const float* image_tokens = (const float*)d_in[0];
    const float* point_tokens = (const float*)d_in[1];
    const float* image_pos    = (const float*)d_in[2];
    const float* point_pos    = (const float*)d_in[3];
    const float* Wip = (const float*)d_in[4];   const float* bip = (const float*)d_in[5];
    const float* Wpp = (const float*)d_in[6];   const float* bpp = (const float*)d_in[7];
    const float* Wq  = (const float*)d_in[8];   const float* bq  = (const float*)d_in[9];
    const float* Wk  = (const float*)d_in[10];  const float* bk  = (const float*)d_in[11];
    const float* Wv  = (const float*)d_in[12];  const float* bv  = (const float*)d_in[13];
    const float* Wo  = (const float*)d_in[14];  const float* bo  = (const float*)d_in[15];
    const float* g1  = (const float*)d_in[16];  const float* b1  = (const float*)d_in[17];
    const float* g2  = (const float*)d_in[18];  const float* b2  = (const float*)d_in[19];
    const float* Wf1 = (const float*)d_in[20];  const float* bf1 = (const float*)d_in[21];
    const float* Wf2 = (const float*)d_in[22];  const float* bf2 = (const float*)d_in[23];
    float* out = (float*)d_out;

    float *tmpA, *tmpB, *qp, *kp, *vp, *attp, *ln1p, *ffp, *wr;
    cudaGetSymbolAddress((void**)&tmpA, g_tmpA);
    cudaGetSymbolAddress((void**)&tmpB, g_tmpB);
    cudaGetSymbolAddress((void**)&qp,   g_q);
    cudaGetSymbolAddress((void**)&kp,   g_k);
    cudaGetSymbolAddress((void**)&vp,   g_v);
    cudaGetSymbolAddress((void**)&attp, g_att);
    cudaGetSymbolAddress((void**)&ln1p, g_ln1);
    cudaGetSymbolAddress((void**)&ffp,  g_ff);
    cudaGetSymbolAddress((void**)&wr,   g_wr);

    float* rWip = wr + 0*WSZ;
    float* rWpp = wr + 1*WSZ;
    float* rWq  = wr + 2*WSZ;
    float* rWk  = wr + 3*WSZ;
    float* rWv  = wr + 4*WSZ;
    float* rWo  = wr + 5*WSZ;
    float* rWf1 = wr + 6*WSZ;
    float* rWf2 = wr + 6*WSZ + WFSZ;

    cudaFuncSetAttribute(tf32gemm<0>, cudaFuncAttributeMaxDynamicSharedMemorySize, GEMM_SMEM);
    cudaFuncSetAttribute(tf32gemm<1>, cudaFuncAttributeMaxDynamicSharedMemorySize, GEMM_SMEM);
    cudaFuncSetAttribute(tf32gemm<2>, cudaFuncAttributeMaxDynamicSharedMemorySize, GEMM_SMEM);
    cudaFuncSetAttribute(tf32gemm<4>, cudaFuncAttributeMaxDynamicSharedMemorySize, GEMM_SMEM);
    cudaFuncSetAttribute(attn_kernel, cudaFuncAttributeMaxDynamicSharedMemorySize, ATT_SMEM);

    const dim3 blk(256);

    // round weights to tf32 (cheap, overlappable)
    roundw_kernel<<<(WSZ+255)/256, 256>>>(Wip, rWip, WSZ);
    roundw_kernel<<<(WSZ+255)/256, 256>>>(Wpp, rWpp, WSZ);
    roundw_kernel<<<(WSZ+255)/256, 256>>>(Wq,  rWq,  WSZ);
    roundw_kernel<<<(WSZ+255)/256, 256>>>(Wk,  rWk,  WSZ);
    roundw_kernel<<<(WSZ+255)/256, 256>>>(Wv,  rWv,  WSZ);
    roundw_kernel<<<(WSZ+255)/256, 256>>>(Wo,  rWo,  WSZ);
    roundw_kernel<<<(WFSZ+255)/256, 256>>>(Wf1, rWf1, WFSZ);
    roundw_kernel<<<(WFSZ+255)/256, 256>>>(Wf2, rWf2, WFSZ);

    // positional projections + residual
    tf32gemm<1><<<dim3(EMBED/128, MQ/128), blk, GEMM_SMEM>>>(image_pos, rWip, bip, image_tokens, tmpA, MQ, EMBED, EMBED);
    tf32gemm<1><<<dim3(EMBED/128, MK/128), blk, GEMM_SMEM>>>(point_pos, rWpp, bpp, point_tokens, tmpB, MK, EMBED, EMBED);
    // q, k, v projections (v rounded to tf32 for attention B-operand)
    tf32gemm<0><<<dim3(EMBED/128, MQ/128), blk, GEMM_SMEM>>>(tmpA, rWq, bq, nullptr, qp, MQ, EMBED, EMBED);
    tf32gemm<0><<<dim3(EMBED/128, MK/128), blk, GEMM_SMEM>>>(tmpB, rWk, bk, nullptr, kp, MK, EMBED, EMBED);
    tf32gemm<4><<<dim3(EMBED/128, MK/128), blk, GEMM_SMEM>>>(point_tokens, rWv, bv, nullptr, vp, MK, EMBED, EMBED);
    // per-head L2 normalization (writes tf32-rounded)
    l2norm_kernel<<<(MQ*HEADS)/8, 256>>>(qp, MQ*HEADS);
    l2norm_kernel<<<(MK*HEADS)/8, 256>>>(kp, MK*HEADS);
    // attention
    attn_kernel<<<dim3(LQ/64, HEADS, BATCH), 128, ATT_SMEM>>>(qp, kp, vp, attp);
    // output projection + residual, LN1
    tf32gemm<1><<<dim3(EMBED/128, MQ/128), blk, GEMM_SMEM>>>(attp, rWo, bo, image_tokens, tmpA, MQ, EMBED, EMBED);
    layernorm_kernel<<<MQ, 256>>>(tmpA, g1, b1, ln1p);
    // FFN
    tf32gemm<2><<<dim3(FF/128, MQ/128), blk, GEMM_SMEM>>>(ln1p, rWf1, bf1, nullptr, ffp, MQ, FF, EMBED);
    tf32gemm<1><<<dim3(EMBED/128, MQ/128), blk, GEMM_SMEM>>>(ffp, rWf2, bf2, ln1p, tmpA, MQ, EMBED, FF);
    layernorm_kernel<<<MQ, 256>>>(tmpA, g2, b2, out);
}

// round 5
// speedup vs baseline: 5.0182x; 1.3375x over previous
#include <cuda_runtime.h>
#include <cuda_fp16.h>
#include <math.h>
#include <stdint.h>

#define EMBED 768
#define HEADS 12
#define HDIM  64
#define FF    1536
#define BATCH 4
#define LQ    2048
#define LK    2048
#define MQ    (BATCH*LQ)   /* 8192 */
#define MK    (BATCH*LK)   /* 8192 */
#define WSZ   (EMBED*EMBED)
#define WFSZ  (EMBED*FF)

// ---------------- scratch (no allocations allowed) ----------------
__device__ float  g_qp [MQ*EMBED];
__device__ float  g_kp [MK*EMBED];
__device__ float  g_vp [MK*EMBED];
__device__ float  g_o  [MQ*EMBED];
__device__ float  g_ln1[MQ*EMBED];
__device__ float  g_f2 [MQ*EMBED];
__device__ __half g_hA [MQ*EMBED];      // tmpA fp16
__device__ __half g_hB [MK*EMBED];      // tmpB fp16
__device__ __half g_hip[MQ*EMBED];      // image_pos fp16
__device__ __half g_hpp[MK*EMBED];      // point_pos fp16
__device__ __half g_hpt[MK*EMBED];      // point_tokens fp16
__device__ __half g_qh [MQ*EMBED];
__device__ __half g_kh [MK*EMBED];
__device__ __half g_vt [BATCH*EMBED*LK];  // V transposed per batch: [b, E, Lk]
__device__ __half g_hat[MQ*EMBED];      // attention out fp16
__device__ __half g_hln[MQ*EMBED];      // ln1 fp16
__device__ __half g_hff[MQ*FF];         // gelu out fp16
__device__ __half g_wh [6*WSZ + 2*WFSZ]; // transposed fp16 weights Wt[n][k]

// ---------------- helpers ----------------
__device__ __forceinline__ void cpasync16(void* s, const void* g) {
    uint32_t sa = (uint32_t)__cvta_generic_to_shared(s);
    asm volatile("cp.async.cg.shared.global [%0], [%1], 16;" :: "r"(sa), "l"(g));
}
#define CP_COMMIT() asm volatile("cp.async.commit_group;")

__device__ __forceinline__ void mma_f16(float c[4], const uint32_t a[4], const uint32_t b[2])
{
    asm volatile(
        "mma.sync.aligned.m16n8k16.row.col.f32.f16.f16.f32 "
        "{%0,%1,%2,%3}, {%4,%5,%6,%7}, {%8,%9}, {%0,%1,%2,%3};"
        : "+f"(c[0]), "+f"(c[1]), "+f"(c[2]), "+f"(c[3])
        : "r"(a[0]), "r"(a[1]), "r"(a[2]), "r"(a[3]), "r"(b[0]), "r"(b[1]));
}

// ---------------- prep: fp16 copies of the three A-side inputs ----------------
__global__ void cvt3(const float* __restrict__ a, const float* __restrict__ b,
                     const float* __restrict__ c, __half* __restrict__ ha,
                     __half* __restrict__ hb, __half* __restrict__ hc)
{
    size_t i = ((size_t)blockIdx.x * 256 + threadIdx.x) * 4;
    if (i >= (size_t)MQ*EMBED) return;
    float4 va = *(const float4*)(a + i);
    float4 vb = *(const float4*)(b + i);
    float4 vc = *(const float4*)(c + i);
    *(__half2*)(ha + i)     = __floats2half2_rn(va.x, va.y);
    *(__half2*)(ha + i + 2) = __floats2half2_rn(va.z, va.w);
    *(__half2*)(hb + i)     = __floats2half2_rn(vb.x, vb.y);
    *(__half2*)(hb + i + 2) = __floats2half2_rn(vb.z, vb.w);
    *(__half2*)(hc + i)     = __floats2half2_rn(vc.x, vc.y);
    *(__half2*)(hc + i + 2) = __floats2half2_rn(vc.z, vc.w);
}

// ---------------- weight transpose + fp16 convert (one launch, 8 matrices) ----------------
struct WPtrs { const float* s[8]; };

__global__ void twr_all(WPtrs P, __half* __restrict__ wh)
{
    const int z = blockIdx.z;
    const int K = (z == 7) ? FF : EMBED;
    const int N = (z == 6) ? FF : EMBED;
    const int n0 = blockIdx.x * 32, k0 = blockIdx.y * 32;
    if (n0 >= N || k0 >= K) return;
    const float* src = P.s[z];
    size_t off = (z <= 5) ? (size_t)z * WSZ : (z == 6 ? (size_t)6*WSZ : (size_t)6*WSZ + WFSZ);
    __half* dst = wh + off;

    __shared__ float t[32][33];
    #pragma unroll
    for (int i = 0; i < 32; i += 8)
        t[threadIdx.y + i][threadIdx.x] =
            src[(size_t)(k0 + threadIdx.y + i) * N + n0 + threadIdx.x];
    __syncthreads();
    #pragma unroll
    for (int i = 0; i < 32; i += 8)
        dst[(size_t)(n0 + threadIdx.y + i) * K + k0 + threadIdx.x] =
            __float2half(t[threadIdx.x][threadIdx.y + i]);
}

// ---------------- fp16 GEMM 128x128x32: C = A[M,K] @ Wt[N,K]^T + bias (+epi) ----------------
// EPI bit0 = +residual R (fp32), bit1 = exact GELU, bit3 = fp16 output
// smem: 2 stages x (A[128][40h] + B[128][40h]) = 40960 B
#define HG_SMEM (4 * 10240)

template<int EPI>
__global__ __launch_bounds__(256)
void hgemm(const __half* __restrict__ A, const __half* __restrict__ Wt,
           const float* __restrict__ bias, const float* __restrict__ R,
           void* __restrict__ Cv, int M, int N, int K)
{
    extern __shared__ char smem[];
    __half* As[2] = { (__half*)smem,                  (__half*)(smem + 20480) };
    __half* Bs[2] = { (__half*)(smem + 10240),        (__half*)(smem + 30720) };

    const int tid  = threadIdx.x;
    const int lane = tid & 31;
    const int warp = tid >> 5;
    const int wm   = warp & 3;          // 4 warps along M (32 rows each)
    const int wn   = warp >> 2;         // 2 warps along N (64 cols each)
    const int bm   = blockIdx.y * 128;
    const int bn   = blockIdx.x * 128;
    const int NT   = K / 32;

    float acc[2][8][4];
    #pragma unroll
    for (int mi = 0; mi < 2; mi++)
        #pragma unroll
        for (int ni = 0; ni < 8; ni++)
            #pragma unroll
            for (int t = 0; t < 4; t++) acc[mi][ni][t] = 0.f;

    // per-thread load coords: 512 chunks of 16B per operand, 2 per thread
    const int r0l = tid >> 2;           // rows 0..63 (+64)
    const int ch  = (tid & 3) * 8;      // halves offset 0,8,16,24

    // prefetch stage 0
    {
        #pragma unroll
        for (int i = 0; i < 2; i++) {
            int r = r0l + 64*i;
            cpasync16((char*)As[0] + r*80 + (ch>>3)*16, A  + (size_t)(bm + r) * K + ch);
            cpasync16((char*)Bs[0] + r*80 + (ch>>3)*16, Wt + (size_t)(bn + r) * K + ch);
        }
        CP_COMMIT();
    }

    for (int s = 0; s < NT; s++) {
        if (s + 1 < NT) {
            const int k0 = (s+1) * 32;
            __half* da = As[(s+1) & 1]; __half* db = Bs[(s+1) & 1];
            #pragma unroll
            for (int i = 0; i < 2; i++) {
                int r = r0l + 64*i;
                cpasync16((char*)da + r*80 + (ch>>3)*16, A  + (size_t)(bm + r) * K + k0 + ch);
                cpasync16((char*)db + r*80 + (ch>>3)*16, Wt + (size_t)(bn + r) * K + k0 + ch);
            }
            CP_COMMIT();
            asm volatile("cp.async.wait_group 1;");
        } else {
            asm volatile("cp.async.wait_group 0;");
        }
        __syncthreads();

        const __half* as = As[s & 1];
        const __half* bs = Bs[s & 1];

        #pragma unroll
        for (int kk = 0; kk < 2; kk++) {
            const int kb = kk * 16 + (lane & 3) * 2;
            uint32_t a[2][4];
            #pragma unroll
            for (int mi = 0; mi < 2; mi++) {
                const __half* ap = as + (wm*32 + mi*16 + (lane>>2))*40 + kb;
                a[mi][0] = *(const uint32_t*)ap;
                a[mi][1] = *(const uint32_t*)(ap + 8*40);
                a[mi][2] = *(const uint32_t*)(ap + 8);
                a[mi][3] = *(const uint32_t*)(ap + 8*40 + 8);
            }
            uint32_t b[8][2];
            #pragma unroll
            for (int ni = 0; ni < 8; ni++) {
                const __half* bp = bs + (wn*64 + ni*8 + (lane>>2))*40 + kb;
                b[ni][0] = *(const uint32_t*)bp;
                b[ni][1] = *(const uint32_t*)(bp + 8);
            }
            #pragma unroll
            for (int mi = 0; mi < 2; mi++)
                #pragma unroll
                for (int ni = 0; ni < 8; ni++)
                    mma_f16(acc[mi][ni], a[mi], b[ni]);
        }
        __syncthreads();
    }

    // epilogue
    #pragma unroll
    for (int mi = 0; mi < 2; mi++) {
        const int r0 = bm + wm*32 + mi*16 + (lane>>2);
        #pragma unroll
        for (int ni = 0; ni < 8; ni++) {
            const int c = bn + wn*64 + ni*8 + 2*(lane & 3);
            const float2 bb = *(const float2*)(bias + c);
            #pragma unroll
            for (int half_ = 0; half_ < 2; half_++) {
                const int r = r0 + half_*8;
                float v0 = acc[mi][ni][2*half_+0] + bb.x;
                float v1 = acc[mi][ni][2*half_+1] + bb.y;
                if (EPI & 1) {
                    const float2 rr = *(const float2*)(R + (size_t)r * N + c);
                    v0 += rr.x; v1 += rr.y;
                }
                if (EPI & 2) {
                    v0 = 0.5f * v0 * (1.f + erff(v0 * 0.70710678118654752f));
                    v1 = 0.5f * v1 * (1.f + erff(v1 * 0.70710678118654752f));
                }
                if (EPI & 8)
                    *(__half2*)((__half*)Cv + (size_t)r * N + c) = __floats2half2_rn(v0, v1);
                else
                    *(float2*)((float*)Cv + (size_t)r * N + c) = make_float2(v0, v1);
            }
        }
    }
}

// ---------------- per-head L2 normalize: fp32 in -> fp16 out ----------------
__global__ void l2norm_kernel(const float* __restrict__ x, __half* __restrict__ y, int nvec)
{
    const int warp = (blockIdx.x * blockDim.x + threadIdx.x) >> 5;
    const int lane = threadIdx.x & 31;
    if (warp >= nvec) return;
    const float* p = x + (size_t)warp * HDIM;
    float a = p[lane], b = p[lane + 32];
    float ss = a*a + b*b;
    #pragma unroll
    for (int m = 16; m; m >>= 1) ss += __shfl_xor_sync(0xffffffffu, ss, m);
    float n   = sqrtf(ss);
    float inv = 1.f / fmaxf(n, 1e-12f);
    __half* q = y + (size_t)warp * HDIM;
    q[lane]      = __float2half(a * inv);
    q[lane + 32] = __float2half(b * inv);
}

// ---------------- V transpose: vp fp32 [b*Lk+t][E] -> vt fp16 [b, E][Lk] ----------------
__global__ void vtrans_kernel(const float* __restrict__ vp, __half* __restrict__ vt)
{
    const int t0 = blockIdx.x * 32;
    const int d0 = blockIdx.y * 32;
    const int b  = blockIdx.z;
    __shared__ float t[32][33];
    #pragma unroll
    for (int i = 0; i < 32; i += 8)
        t[threadIdx.y + i][threadIdx.x] =
            vp[(size_t)(b*LK + t0 + threadIdx.y + i) * EMBED + d0 + threadIdx.x];
    __syncthreads();
    #pragma unroll
    for (int i = 0; i < 32; i += 8)
        vt[(size_t)(b*EMBED + d0 + threadIdx.y + i) * LK + t0 + threadIdx.x] =
            __float2half(t[threadIdx.x][threadIdx.y + i]);
}

// ---------------- LayerNorm over 768 (optionally dual fp32 + fp16 out) ----------------
template<bool DUAL>
__global__ void layernorm_kernel(const float* __restrict__ x,
                                 const float* __restrict__ g,
                                 const float* __restrict__ b,
                                 float* __restrict__ y, __half* __restrict__ yh)
{
    const int row = blockIdx.x;
    const float* xr = x + (size_t)row * EMBED;
    const int tid = threadIdx.x;

    float v0 = xr[tid], v1 = xr[tid + 256], v2 = xr[tid + 512];

    __shared__ float red[8];
    float s = v0 + v1 + v2;
    #pragma unroll
    for (int m = 16; m; m >>= 1) s += __shfl_xor_sync(0xffffffffu, s, m);
    if ((tid & 31) == 0) red[tid >> 5] = s;
    __syncthreads();
    s = 0.f;
    #pragma unroll
    for (int w = 0; w < 8; w++) s += red[w];
    const float mu = s * (1.f / EMBED);
    __syncthreads();

    float d0 = v0 - mu, d1 = v1 - mu, d2 = v2 - mu;
    float ss = d0*d0 + d1*d1 + d2*d2;
    #pragma unroll
    for (int m = 16; m; m >>= 1) ss += __shfl_xor_sync(0xffffffffu, ss, m);
    if ((tid & 31) == 0) red[tid >> 5] = ss;
    __syncthreads();
    ss = 0.f;
    #pragma unroll
    for (int w = 0; w < 8; w++) ss += red[w];
    const float inv = rsqrtf(ss * (1.f / EMBED) + 1e-5f);

    float o0 = d0 * inv * g[tid]       + b[tid];
    float o1 = d1 * inv * g[tid + 256] + b[tid + 256];
    float o2 = d2 * inv * g[tid + 512] + b[tid + 512];
    float* yr = y + (size_t)row * EMBED;
    yr[tid] = o0; yr[tid + 256] = o1; yr[tid + 512] = o2;
    if (DUAL) {
        __half* hr = yh + (size_t)row * EMBED;
        hr[tid] = __float2half(o0);
        hr[tid + 256] = __float2half(o1);
        hr[tid + 512] = __float2half(o2);
    }
}

// ---------------- fp16 flash attention (scale-free: p = exp(s-1), no online max) ----------------
// 128 threads / 4 warps; q-tile 64 (16 rows/warp); kv-tile 64, double-buffered.
// Qs[64][72]h, Ks x2 [64][72]h, Vt x2 [64 d][72]h (d-major), Ps [64][72]h
#define ATT_SMEM (7 * 64 * 72 * 2)

__global__ __launch_bounds__(128)
void attn_kernel(const __half* __restrict__ q, const __half* __restrict__ k,
                 const __half* __restrict__ vt, __half* __restrict__ out)
{
    extern __shared__ __half hsm[];
    __half* Qs    = hsm;
    __half* Ks[2] = { Qs + 64*72,      Qs + 2*64*72 };
    __half* Vs[2] = { Qs + 3*64*72,    Qs + 4*64*72 };
    __half* Ps    = Qs + 5*64*72;   // 4 warps x 16 rows x 72

    const int tid  = threadIdx.x;
    const int lane = tid & 31;
    const int warp = tid >> 5;
    const int q0 = blockIdx.x * 64;
    const int h  = blockIdx.y;
    const int b  = blockIdx.z;

    const __half* qb  = q  + ((size_t)(b*LQ + q0)) * EMBED + h * HDIM;
    const __half* kb  = k  + ((size_t)(b*LK))      * EMBED + h * HDIM;
    const __half* vtb = vt + ((size_t)(b*EMBED + h*HDIM)) * LK;

    const int rl = tid >> 3;            // 0..15
    const int cl = (tid & 7) * 8;       // halves 0..56

    // Q tile + stage-0 K/V
    #pragma unroll
    for (int i = 0; i < 4; i++) {
        int r = rl + 16*i;
        cpasync16(Qs + r*72 + cl, qb + (size_t)r * EMBED + cl);
    }
    #pragma unroll
    for (int i = 0; i < 4; i++) {
        int r = rl + 16*i;
        cpasync16(Ks[0] + r*72 + cl, kb  + (size_t)r * EMBED + cl);
        cpasync16(Vs[0] + r*72 + cl, vtb + (size_t)r * LK + cl);
    }
    CP_COMMIT();

    float o[8][4];
    #pragma unroll
    for (int ni = 0; ni < 8; ni++)
        #pragma unroll
        for (int t = 0; t < 4; t++) o[ni][t] = 0.f;
    float l0 = 0.f, l1 = 0.f;

    __half* Pw = Ps + warp*16*72;
    const int rql = lane >> 2;          // warp-local row group 0..7

    for (int kt = 0; kt < LK/64; kt++) {
        asm volatile("cp.async.wait_group 0;");
        __syncthreads();

        const __half* ks = Ks[kt & 1];
        const __half* vs = Vs[kt & 1];

        if (kt + 1 < LK/64) {
            __half* ksn = Ks[(kt+1) & 1];
            __half* vsn = Vs[(kt+1) & 1];
            const __half* kp = kb  + (size_t)(kt+1) * 64 * EMBED;
            const __half* vp = vtb + (size_t)(kt+1) * 64;
            #pragma unroll
            for (int i = 0; i < 4; i++) {
                int r = rl + 16*i;
                cpasync16(ksn + r*72 + cl, kp + (size_t)r * EMBED + cl);
                cpasync16(vsn + r*72 + cl, vp + (size_t)r * LK + cl);
            }
            CP_COMMIT();
        }

        // S = Q @ K^T   (16 q-rows x 64 keys per warp)
        float s[8][4];
        #pragma unroll
        for (int ni = 0; ni < 8; ni++)
            #pragma unroll
            for (int t = 0; t < 4; t++) s[ni][t] = 0.f;

        #pragma unroll
        for (int kk = 0; kk < 4; kk++) {
            const int kb2 = kk*16 + (lane & 3)*2;
            uint32_t a[4];
            const __half* ap = Qs + (warp*16 + rql)*72 + kb2;
            a[0] = *(const uint32_t*)ap;
            a[1] = *(const uint32_t*)(ap + 8*72);
            a[2] = *(const uint32_t*)(ap + 8);
            a[3] = *(const uint32_t*)(ap + 8*72 + 8);
            #pragma unroll
            for (int ni = 0; ni < 8; ni++) {
                const __half* bp = ks + (ni*8 + rql)*72 + kb2;
                uint32_t bf[2] = { *(const uint32_t*)bp, *(const uint32_t*)(bp + 8) };
                mma_f16(s[ni], a, bf);
            }
        }

        // p = exp(s - 1); row sums; store fp16 P
        #pragma unroll
        for (int ni = 0; ni < 8; ni++) {
            float p0 = __expf(s[ni][0] - 1.f);
            float p1 = __expf(s[ni][1] - 1.f);
            float p2 = __expf(s[ni][2] - 1.f);
            float p3 = __expf(s[ni][3] - 1.f);
            l0 += p0 + p1;
            l1 += p2 + p3;
            __half* pp = Pw + rql*72 + ni*8 + 2*(lane & 3);
            *(__half2*)pp          = __floats2half2_rn(p0, p1);
            *(__half2*)(pp + 8*72) = __floats2half2_rn(p2, p3);
        }
        __syncwarp();

        // O += P @ V  (A = P [16 q][64 keys], B = Vt [d][key] d-major)
        #pragma unroll
        for (int kk = 0; kk < 4; kk++) {
            const int kb2 = kk*16 + (lane & 3)*2;
            uint32_t a[4];
            const __half* ap = Pw + rql*72 + kb2;
            a[0] = *(const uint32_t*)ap;
            a[1] = *(const uint32_t*)(ap + 8*72);
            a[2] = *(const uint32_t*)(ap + 8);
            a[3] = *(const uint32_t*)(ap + 8*72 + 8);
            #pragma unroll
            for (int ni = 0; ni < 8; ni++) {
                const __half* bp = vs + (ni*8 + rql)*72 + kb2;
                uint32_t bf[2] = { *(const uint32_t*)bp, *(const uint32_t*)(bp + 8) };
                mma_f16(o[ni], a, bf);
            }
        }
        __syncthreads();
    }

    l0 += __shfl_xor_sync(0xffffffffu, l0, 1);
    l0 += __shfl_xor_sync(0xffffffffu, l0, 2);
    l1 += __shfl_xor_sync(0xffffffffu, l1, 1);
    l1 += __shfl_xor_sync(0xffffffffu, l1, 2);
    const float inv0 = 1.f / l0, inv1 = 1.f / l1;

    const int r = b*LQ + q0 + warp*16 + rql;
    #pragma unroll
    for (int ni = 0; ni < 8; ni++) {
        const int c = h*HDIM + ni*8 + 2*(lane & 3);
        *(__half2*)(out + (size_t)r * EMBED + c)     = __floats2half2_rn(o[ni][0]*inv0, o[ni][1]*inv0);
        *(__half2*)(out + (size_t)(r+8) * EMBED + c) = __floats2half2_rn(o[ni][2]*inv1, o[ni][3]*inv1);
    }
}

// ---------------- launch ----------------
extern "C" void kernel_launch(void* const* d_in, const int* in_sizes, int n_in,
                              void* d_out, int out_size)
{
    const float* image_tokens = (const float*)d_in[0];
    const float* point_tokens = (const float*)d_in[1];
    const float* image_pos    = (const float*)d_in[2];
    const float* point_pos    = (const float*)d_in[3];
    const float* Wip = (const float*)d_in[4];   const float* bip = (const float*)d_in[5];
    const float* Wpp = (const float*)d_in[6];   const float* bpp = (const float*)d_in[7];
    const float* Wq  = (const float*)d_in[8];   const float* bq  = (const float*)d_in[9];
    const float* Wk  = (const float*)d_in[10];  const float* bk  = (const float*)d_in[11];
    const float* Wv  = (const float*)d_in[12];  const float* bv  = (const float*)d_in[13];
    const float* Wo  = (const float*)d_in[14];  const float* bo  = (const float*)d_in[15];
    const float* g1  = (const float*)d_in[16];  const float* b1  = (const float*)d_in[17];
    const float* g2  = (const float*)d_in[18];  const float* b2  = (const float*)d_in[19];
    const float* Wf1 = (const float*)d_in[20];  const float* bf1 = (const float*)d_in[21];
    const float* Wf2 = (const float*)d_in[22];  const float* bf2 = (const float*)d_in[23];
    float* out = (float*)d_out;

    float  *qp, *kp, *vp, *op, *ln1p, *f2p;
    __half *hA, *hB, *hip, *hpp, *hpt, *qh, *kh, *vt, *hat, *hln, *hff, *wh;
    cudaGetSymbolAddress((void**)&qp,  g_qp);
    cudaGetSymbolAddress((void**)&kp,  g_kp);
    cudaGetSymbolAddress((void**)&vp,  g_vp);
    cudaGetSymbolAddress((void**)&op,  g_o);
    cudaGetSymbolAddress((void**)&ln1p,g_ln1);
    cudaGetSymbolAddress((void**)&f2p, g_f2);
    cudaGetSymbolAddress((void**)&hA,  g_hA);
    cudaGetSymbolAddress((void**)&hB,  g_hB);
    cudaGetSymbolAddress((void**)&hip, g_hip);
    cudaGetSymbolAddress((void**)&hpp, g_hpp);
    cudaGetSymbolAddress((void**)&hpt, g_hpt);
    cudaGetSymbolAddress((void**)&qh,  g_qh);
    cudaGetSymbolAddress((void**)&kh,  g_kh);
    cudaGetSymbolAddress((void**)&vt,  g_vt);
    cudaGetSymbolAddress((void**)&hat, g_hat);
    cudaGetSymbolAddress((void**)&hln, g_hln);
    cudaGetSymbolAddress((void**)&hff, g_hff);
    cudaGetSymbolAddress((void**)&wh,  g_wh);

    __half* WipT = wh + 0*WSZ;
    __half* WppT = wh + 1*WSZ;
    __half* WqT  = wh + 2*WSZ;
    __half* WkT  = wh + 3*WSZ;
    __half* WvT  = wh + 4*WSZ;
    __half* WoT  = wh + 5*WSZ;
    __half* Wf1T = wh + 6*WSZ;
    __half* Wf2T = wh + 6*WSZ + WFSZ;

    cudaFuncSetAttribute(attn_kernel, cudaFuncAttributeMaxDynamicSharedMemorySize, ATT_SMEM);

    // prep
    WPtrs P;
    P.s[0]=Wip; P.s[1]=Wpp; P.s[2]=Wq; P.s[3]=Wk; P.s[4]=Wv; P.s[5]=Wo; P.s[6]=Wf1; P.s[7]=Wf2;
    twr_all<<<dim3(48, 48, 8), dim3(32, 8)>>>(P, wh);
    cvt3<<<(MQ*EMBED/4 + 255)/256, 256>>>(image_pos, point_pos, point_tokens, hip, hpp, hpt);

    // positional projections + residual -> fp16
    hgemm<9><<<dim3(EMBED/128, MQ/128), 256, HG_SMEM>>>(hip, WipT, bip, image_tokens, hA, MQ, EMBED, EMBED);
    hgemm<9><<<dim3(EMBED/128, MK/128), 256, HG_SMEM>>>(hpp, WppT, bpp, point_tokens, hB, MK, EMBED, EMBED);
    // q, k, v projections -> fp32
    hgemm<0><<<dim3(EMBED/128, MQ/128), 256, HG_SMEM>>>(hA, WqT, bq, nullptr, qp, MQ, EMBED, EMBED);
    hgemm<0><<<dim3(EMBED/128, MK/128), 256, HG_SMEM>>>(hB, WkT, bk, nullptr, kp, MK, EMBED, EMBED);
    hgemm<0><<<dim3(EMBED/128, MK/128), 256, HG_SMEM>>>(hpt, WvT, bv, nullptr, vp, MK, EMBED, EMBED);
    // l2 normalize -> fp16; V transpose -> fp16
    l2norm_kernel<<<(MQ*HEADS)/8, 256>>>(qp, qh, MQ*HEADS);
    l2norm_kernel<<<(MK*HEADS)/8, 256>>>(kp, kh, MK*HEADS);
    vtrans_kernel<<<dim3(LK/32, EMBED/32, BATCH), dim3(32, 8)>>>(vp, vt);
    // attention -> fp16
    attn_kernel<<<dim3(LQ/64, HEADS, BATCH), 128, ATT_SMEM>>>(qh, kh, vt, hat);
    // output projection + residual -> fp32, LN1 (dual out)
    hgemm<1><<<dim3(EMBED/128, MQ/128), 256, HG_SMEM>>>(hat, WoT, bo, image_tokens, op, MQ, EMBED, EMBED);
    layernorm_kernel<true><<<MQ, 256>>>(op, g1, b1, ln1p, hln);
    // FFN
    hgemm<10><<<dim3(FF/128, MQ/128), 256, HG_SMEM>>>(hln, Wf1T, bf1, nullptr, hff, MQ, FF, EMBED);
    hgemm<1><<<dim3(EMBED/128, MQ/128), 256, HG_SMEM>>>(hff, Wf2T, bf2, ln1p, f2p, MQ, EMBED, FF);
    layernorm_kernel<false><<<MQ, 256>>>(f2p, g2, b2, out, nullptr);
}

// round 6
// speedup vs baseline: 5.6330x; 1.1225x over previous
#include <cuda_runtime.h>
#include <cuda_fp16.h>
#include <math.h>
#include <stdint.h>

#define EMBED 768
#define HEADS 12
#define HDIM  64
#define FF    1536
#define BATCH 4
#define LQ    2048
#define LK    2048
#define MQ    (BATCH*LQ)   /* 8192 */
#define MK    (BATCH*LK)   /* 8192 */
#define WSZ   (EMBED*EMBED)
#define WFSZ  (EMBED*FF)

// ---------------- scratch (no allocations allowed) ----------------
__device__ float  g_qp [MQ*EMBED];
__device__ float  g_kp [MK*EMBED];
__device__ float  g_vp [MK*EMBED];
__device__ float  g_o  [MQ*EMBED];
__device__ float  g_ln1[MQ*EMBED];
__device__ float  g_f2 [MQ*EMBED];
__device__ __half g_hA [MQ*EMBED];
__device__ __half g_hB [MK*EMBED];
__device__ __half g_hip[MQ*EMBED];
__device__ __half g_hpp[MK*EMBED];
__device__ __half g_hpt[MK*EMBED];
__device__ __half g_qh [MQ*EMBED];
__device__ __half g_kh [MK*EMBED];
__device__ __half g_vt [BATCH*EMBED*LK];
__device__ __half g_hat[MQ*EMBED];
__device__ __half g_hln[MQ*EMBED];
__device__ __half g_hff[MQ*FF];
__device__ __half g_wh [6*WSZ + 2*WFSZ];

// ---------------- helpers ----------------
__device__ __forceinline__ void cpasync16(void* s, const void* g) {
    uint32_t sa = (uint32_t)__cvta_generic_to_shared(s);
    asm volatile("cp.async.cg.shared.global [%0], [%1], 16;" :: "r"(sa), "l"(g));
}
#define CP_COMMIT() asm volatile("cp.async.commit_group;")

__device__ __forceinline__ uint32_t smem_u32(const void* p) {
    return (uint32_t)__cvta_generic_to_shared(p);
}

__device__ __forceinline__ void mma_f16(float c[4], const uint32_t a[4], const uint32_t b[2])
{
    asm volatile(
        "mma.sync.aligned.m16n8k16.row.col.f32.f16.f16.f32 "
        "{%0,%1,%2,%3}, {%4,%5,%6,%7}, {%8,%9}, {%0,%1,%2,%3};"
        : "+f"(c[0]), "+f"(c[1]), "+f"(c[2]), "+f"(c[3])
        : "r"(a[0]), "r"(a[1]), "r"(a[2]), "r"(a[3]), "r"(b[0]), "r"(b[1]));
}

__device__ __forceinline__ void ldsm_x4(uint32_t r[4], uint32_t addr) {
    asm volatile("ldmatrix.sync.aligned.m8n8.x4.shared.b16 {%0,%1,%2,%3}, [%4];"
        : "=r"(r[0]), "=r"(r[1]), "=r"(r[2]), "=r"(r[3]) : "r"(addr));
}

// ---------------- prep: fp16 copies of the three A-side inputs ----------------
__global__ void cvt3(const float* __restrict__ a, const float* __restrict__ b,
                     const float* __restrict__ c, __half* __restrict__ ha,
                     __half* __restrict__ hb, __half* __restrict__ hc)
{
    size_t i = ((size_t)blockIdx.x * 256 + threadIdx.x) * 4;
    if (i >= (size_t)MQ*EMBED) return;
    float4 va = *(const float4*)(a + i);
    float4 vb = *(const float4*)(b + i);
    float4 vc = *(const float4*)(c + i);
    *(__half2*)(ha + i)     = __floats2half2_rn(va.x, va.y);
    *(__half2*)(ha + i + 2) = __floats2half2_rn(va.z, va.w);
    *(__half2*)(hb + i)     = __floats2half2_rn(vb.x, vb.y);
    *(__half2*)(hb + i + 2) = __floats2half2_rn(vb.z, vb.w);
    *(__half2*)(hc + i)     = __floats2half2_rn(vc.x, vc.y);
    *(__half2*)(hc + i + 2) = __floats2half2_rn(vc.z, vc.w);
}

// ---------------- weight transpose + fp16 convert ----------------
struct WPtrs { const float* s[8]; };

__global__ void twr_all(WPtrs P, __half* __restrict__ wh)
{
    const int z = blockIdx.z;
    const int K = (z == 7) ? FF : EMBED;
    const int N = (z == 6) ? FF : EMBED;
    const int n0 = blockIdx.x * 32, k0 = blockIdx.y * 32;
    if (n0 >= N || k0 >= K) return;
    const float* src = P.s[z];
    size_t off = (z <= 5) ? (size_t)z * WSZ : (z == 6 ? (size_t)6*WSZ : (size_t)6*WSZ + WFSZ);
    __half* dst = wh + off;

    __shared__ float t[32][33];
    #pragma unroll
    for (int i = 0; i < 32; i += 8)
        t[threadIdx.y + i][threadIdx.x] =
            src[(size_t)(k0 + threadIdx.y + i) * N + n0 + threadIdx.x];
    __syncthreads();
    #pragma unroll
    for (int i = 0; i < 32; i += 8)
        dst[(size_t)(n0 + threadIdx.y + i) * K + k0 + threadIdx.x] =
            __float2half(t[threadIdx.x][threadIdx.y + i]);
}

// ---------------- fp16 GEMM 128x128x32, ldmatrix + 3-stage cp.async ----------------
// EPI bit0 = +residual R (fp32), bit1 = exact GELU, bit3 = fp16 output
// per stage: A[128][40h] (10240 B) + B[128][40h] -> 20480 B; 3 stages = 61440 B
#define HG_SMEM (3 * 20480)

template<int EPI>
__global__ __launch_bounds__(256)
void hgemm(const __half* __restrict__ A, const __half* __restrict__ Wt,
           const float* __restrict__ bias, const float* __restrict__ R,
           void* __restrict__ Cv, int M, int N, int K)
{
    extern __shared__ char smem[];

    const int tid  = threadIdx.x;
    const int lane = tid & 31;
    const int warp = tid >> 5;
    const int wm   = warp & 3;          // 4 warps along M (32 rows each)
    const int wn   = warp >> 2;         // 2 warps along N (64 cols each)
    const int bm   = blockIdx.y * 128;
    const int bn   = blockIdx.x * 128;
    const int NT   = K / 32;

    float acc[2][8][4];
    #pragma unroll
    for (int mi = 0; mi < 2; mi++)
        #pragma unroll
        for (int ni = 0; ni < 8; ni++)
            #pragma unroll
            for (int t = 0; t < 4; t++) acc[mi][ni][t] = 0.f;

    // cp.async coords: 2 chunks of 16B per operand per thread
    const int lr = tid >> 2;            // rows 0..63 (+64)
    const int lc = tid & 3;             // 16B chunk 0..3

    // ldmatrix per-lane address offsets (within a buffer)
    const int g  = lane >> 3;           // matrix group 0..3
    const int ri = lane & 7;
    const int rowA_off = (wm*32 + (g & 1)*8 + ri) * 80 + (g >> 1)*16;
    const int rowB_off = 10240 + (wn*64 + (g >> 1)*8 + ri) * 80 + (g & 1)*16;

    #define HG_PREFETCH(s)  do {                                                     \
        char* _b = smem + ((s) % 3) * 20480;                                         \
        const int _k0 = (s) * 32;                                                    \
        _Pragma("unroll")                                                            \
        for (int _i = 0; _i < 2; _i++) {                                             \
            int _r = lr + 64*_i;                                                     \
            cpasync16(_b + _r*80 + lc*16,         A  + (size_t)(bm + _r) * K + _k0 + lc*8); \
            cpasync16(_b + 10240 + _r*80 + lc*16, Wt + (size_t)(bn + _r) * K + _k0 + lc*8); \
        }                                                                            \
        CP_COMMIT();                                                                 \
    } while (0)

    HG_PREFETCH(0);
    HG_PREFETCH(1);

    for (int s = 0; s < NT; s++) {
        asm volatile("cp.async.wait_group 1;");
        __syncthreads();
        if (s + 2 < NT) HG_PREFETCH(s + 2);

        const uint32_t buf = smem_u32(smem + (s % 3) * 20480);

        #pragma unroll
        for (int kk = 0; kk < 2; kk++) {
            uint32_t a[2][4];
            #pragma unroll
            for (int mi = 0; mi < 2; mi++)
                ldsm_x4(a[mi], buf + rowA_off + mi*16*80 + kk*32);
            uint32_t b[4][4];
            #pragma unroll
            for (int p = 0; p < 4; p++)
                ldsm_x4(b[p], buf + rowB_off + p*16*80 + kk*32);
            #pragma unroll
            for (int mi = 0; mi < 2; mi++)
                #pragma unroll
                for (int ni = 0; ni < 8; ni++)
                    mma_f16(acc[mi][ni], a[mi], &b[ni >> 1][(ni & 1)*2]);
        }
    }
    #undef HG_PREFETCH

    // epilogue
    #pragma unroll
    for (int mi = 0; mi < 2; mi++) {
        const int r0 = bm + wm*32 + mi*16 + (lane>>2);
        #pragma unroll
        for (int ni = 0; ni < 8; ni++) {
            const int c = bn + wn*64 + ni*8 + 2*(lane & 3);
            const float2 bb = *(const float2*)(bias + c);
            #pragma unroll
            for (int half_ = 0; half_ < 2; half_++) {
                const int r = r0 + half_*8;
                float v0 = acc[mi][ni][2*half_+0] + bb.x;
                float v1 = acc[mi][ni][2*half_+1] + bb.y;
                if (EPI & 1) {
                    const float2 rr = *(const float2*)(R + (size_t)r * N + c);
                    v0 += rr.x; v1 += rr.y;
                }
                if (EPI & 2) {
                    v0 = 0.5f * v0 * (1.f + erff(v0 * 0.70710678118654752f));
                    v1 = 0.5f * v1 * (1.f + erff(v1 * 0.70710678118654752f));
                }
                if (EPI & 8)
                    *(__half2*)((__half*)Cv + (size_t)r * N + c) = __floats2half2_rn(v0, v1);
                else
                    *(float2*)((float*)Cv + (size_t)r * N + c) = make_float2(v0, v1);
            }
        }
    }
}

// ---------------- per-head L2 normalize: fp32 in -> fp16 out ----------------
__global__ void l2norm_kernel(const float* __restrict__ x, __half* __restrict__ y, int nvec)
{
    const int warp = (blockIdx.x * blockDim.x + threadIdx.x) >> 5;
    const int lane = threadIdx.x & 31;
    if (warp >= nvec) return;
    const float* p = x + (size_t)warp * HDIM;
    float a = p[lane], b = p[lane + 32];
    float ss = a*a + b*b;
    #pragma unroll
    for (int m = 16; m; m >>= 1) ss += __shfl_xor_sync(0xffffffffu, ss, m);
    float n   = sqrtf(ss);
    float inv = 1.f / fmaxf(n, 1e-12f);
    __half* q = y + (size_t)warp * HDIM;
    q[lane]      = __float2half(a * inv);
    q[lane + 32] = __float2half(b * inv);
}

// ---------------- V transpose: vp fp32 [b*Lk+t][E] -> vt fp16 [b, E][Lk] ----------------
__global__ void vtrans_kernel(const float* __restrict__ vp, __half* __restrict__ vt)
{
    const int t0 = blockIdx.x * 32;
    const int d0 = blockIdx.y * 32;
    const int b  = blockIdx.z;
    __shared__ float t[32][33];
    #pragma unroll
    for (int i = 0; i < 32; i += 8)
        t[threadIdx.y + i][threadIdx.x] =
            vp[(size_t)(b*LK + t0 + threadIdx.y + i) * EMBED + d0 + threadIdx.x];
    __syncthreads();
    #pragma unroll
    for (int i = 0; i < 32; i += 8)
        vt[(size_t)(b*EMBED + d0 + threadIdx.y + i) * LK + t0 + threadIdx.x] =
            __float2half(t[threadIdx.x][threadIdx.y + i]);
}

// ---------------- LayerNorm over 768 (optionally dual fp32 + fp16 out) ----------------
template<bool DUAL>
__global__ void layernorm_kernel(const float* __restrict__ x,
                                 const float* __restrict__ g,
                                 const float* __restrict__ b,
                                 float* __restrict__ y, __half* __restrict__ yh)
{
    const int row = blockIdx.x;
    const float* xr = x + (size_t)row * EMBED;
    const int tid = threadIdx.x;

    float v0 = xr[tid], v1 = xr[tid + 256], v2 = xr[tid + 512];

    __shared__ float red[8];
    float s = v0 + v1 + v2;
    #pragma unroll
    for (int m = 16; m; m >>= 1) s += __shfl_xor_sync(0xffffffffu, s, m);
    if ((tid & 31) == 0) red[tid >> 5] = s;
    __syncthreads();
    s = 0.f;
    #pragma unroll
    for (int w = 0; w < 8; w++) s += red[w];
    const float mu = s * (1.f / EMBED);
    __syncthreads();

    float d0 = v0 - mu, d1 = v1 - mu, d2 = v2 - mu;
    float ss = d0*d0 + d1*d1 + d2*d2;
    #pragma unroll
    for (int m = 16; m; m >>= 1) ss += __shfl_xor_sync(0xffffffffu, ss, m);
    if ((tid & 31) == 0) red[tid >> 5] = ss;
    __syncthreads();
    ss = 0.f;
    #pragma unroll
    for (int w = 0; w < 8; w++) ss += red[w];
    const float inv = rsqrtf(ss * (1.f / EMBED) + 1e-5f);

    float o0 = d0 * inv * g[tid]       + b[tid];
    float o1 = d1 * inv * g[tid + 256] + b[tid + 256];
    float o2 = d2 * inv * g[tid + 512] + b[tid + 512];
    float* yr = y + (size_t)row * EMBED;
    yr[tid] = o0; yr[tid + 256] = o1; yr[tid + 512] = o2;
    if (DUAL) {
        __half* hr = yh + (size_t)row * EMBED;
        hr[tid] = __float2half(o0);
        hr[tid + 256] = __float2half(o1);
        hr[tid + 512] = __float2half(o2);
    }
}

// ---------------- fp16 flash attention (scale-free: p = exp(s-1), no online max) ----------------
#define ATT_SMEM (7 * 64 * 72 * 2)

__global__ __launch_bounds__(128)
void attn_kernel(const __half* __restrict__ q, const __half* __restrict__ k,
                 const __half* __restrict__ vt, __half* __restrict__ out)
{
    extern __shared__ __half hsm[];
    __half* Qs    = hsm;
    __half* Ks[2] = { Qs + 64*72,      Qs + 2*64*72 };
    __half* Vs[2] = { Qs + 3*64*72,    Qs + 4*64*72 };
    __half* Ps    = Qs + 5*64*72;

    const int tid  = threadIdx.x;
    const int lane = tid & 31;
    const int warp = tid >> 5;
    const int q0 = blockIdx.x * 64;
    const int h  = blockIdx.y;
    const int b  = blockIdx.z;

    const __half* qb  = q  + ((size_t)(b*LQ + q0)) * EMBED + h * HDIM;
    const __half* kb  = k  + ((size_t)(b*LK))      * EMBED + h * HDIM;
    const __half* vtb = vt + ((size_t)(b*EMBED + h*HDIM)) * LK;

    const int rl = tid >> 3;
    const int cl = (tid & 7) * 8;

    #pragma unroll
    for (int i = 0; i < 4; i++) {
        int r = rl + 16*i;
        cpasync16(Qs + r*72 + cl, qb + (size_t)r * EMBED + cl);
    }
    #pragma unroll
    for (int i = 0; i < 4; i++) {
        int r = rl + 16*i;
        cpasync16(Ks[0] + r*72 + cl, kb  + (size_t)r * EMBED + cl);
        cpasync16(Vs[0] + r*72 + cl, vtb + (size_t)r * LK + cl);
    }
    CP_COMMIT();

    float o[8][4];
    #pragma unroll
    for (int ni = 0; ni < 8; ni++)
        #pragma unroll
        for (int t = 0; t < 4; t++) o[ni][t] = 0.f;
    float l0 = 0.f, l1 = 0.f;

    __half* Pw = Ps + warp*16*72;
    const int rql = lane >> 2;

    for (int kt = 0; kt < LK/64; kt++) {
        asm volatile("cp.async.wait_group 0;");
        __syncthreads();

        const __half* ks = Ks[kt & 1];
        const __half* vs = Vs[kt & 1];

        if (kt + 1 < LK/64) {
            __half* ksn = Ks[(kt+1) & 1];
            __half* vsn = Vs[(kt+1) & 1];
            const __half* kp = kb  + (size_t)(kt+1) * 64 * EMBED;
            const __half* vp = vtb + (size_t)(kt+1) * 64;
            #pragma unroll
            for (int i = 0; i < 4; i++) {
                int r = rl + 16*i;
                cpasync16(ksn + r*72 + cl, kp + (size_t)r * EMBED + cl);
                cpasync16(vsn + r*72 + cl, vp + (size_t)r * LK + cl);
            }
            CP_COMMIT();
        }

        float s[8][4];
        #pragma unroll
        for (int ni = 0; ni < 8; ni++)
            #pragma unroll
            for (int t = 0; t < 4; t++) s[ni][t] = 0.f;

        #pragma unroll
        for (int kk = 0; kk < 4; kk++) {
            const int kb2 = kk*16 + (lane & 3)*2;
            uint32_t a[4];
            const __half* ap = Qs + (warp*16 + rql)*72 + kb2;
            a[0] = *(const uint32_t*)ap;
            a[1] = *(const uint32_t*)(ap + 8*72);
            a[2] = *(const uint32_t*)(ap + 8);
            a[3] = *(const uint32_t*)(ap + 8*72 + 8);
            #pragma unroll
            for (int ni = 0; ni < 8; ni++) {
                const __half* bp = ks + (ni*8 + rql)*72 + kb2;
                uint32_t bf[2] = { *(const uint32_t*)bp, *(const uint32_t*)(bp + 8) };
                mma_f16(s[ni], a, bf);
            }
        }

        #pragma unroll
        for (int ni = 0; ni < 8; ni++) {
            float p0 = __expf(s[ni][0] - 1.f);
            float p1 = __expf(s[ni][1] - 1.f);
            float p2 = __expf(s[ni][2] - 1.f);
            float p3 = __expf(s[ni][3] - 1.f);
            l0 += p0 + p1;
            l1 += p2 + p3;
            __half* pp = Pw + rql*72 + ni*8 + 2*(lane & 3);
            *(__half2*)pp          = __floats2half2_rn(p0, p1);
            *(__half2*)(pp + 8*72) = __floats2half2_rn(p2, p3);
        }
        __syncwarp();

        #pragma unroll
        for (int kk = 0; kk < 4; kk++) {
            const int kb2 = kk*16 + (lane & 3)*2;
            uint32_t a[4];
            const __half* ap = Pw + rql*72 + kb2;
            a[0] = *(const uint32_t*)ap;
            a[1] = *(const uint32_t*)(ap + 8*72);
            a[2] = *(const uint32_t*)(ap + 8);
            a[3] = *(const uint32_t*)(ap + 8*72 + 8);
            #pragma unroll
            for (int ni = 0; ni < 8; ni++) {
                const __half* bp = vs + (ni*8 + rql)*72 + kb2;
                uint32_t bf[2] = { *(const uint32_t*)bp, *(const uint32_t*)(bp + 8) };
                mma_f16(o[ni], a, bf);
            }
        }
        __syncthreads();
    }

    l0 += __shfl_xor_sync(0xffffffffu, l0, 1);
    l0 += __shfl_xor_sync(0xffffffffu, l0, 2);
    l1 += __shfl_xor_sync(0xffffffffu, l1, 1);
    l1 += __shfl_xor_sync(0xffffffffu, l1, 2);
    const float inv0 = 1.f / l0, inv1 = 1.f / l1;

    const int r = b*LQ + q0 + warp*16 + rql;
    #pragma unroll
    for (int ni = 0; ni < 8; ni++) {
        const int c = h*HDIM + ni*8 + 2*(lane & 3);
        *(__half2*)(out + (size_t)r * EMBED + c)     = __floats2half2_rn(o[ni][0]*inv0, o[ni][1]*inv0);
        *(__half2*)(out + (size_t)(r+8) * EMBED + c) = __floats2half2_rn(o[ni][2]*inv1, o[ni][3]*inv1);
    }
}

// ---------------- launch ----------------
extern "C" void kernel_launch(void* const* d_in, const int* in_sizes, int n_in,
                              void* d_out, int out_size)
{
    const float* image_tokens = (const float*)d_in[0];
    const float* point_tokens = (const float*)d_in[1];
    const float* image_pos    = (const float*)d_in[2];
    const float* point_pos    = (const float*)d_in[3];
    const float* Wip = (const float*)d_in[4];   const float* bip = (const float*)d_in[5];
    const float* Wpp = (const float*)d_in[6];   const float* bpp = (const float*)d_in[7];
    const float* Wq  = (const float*)d_in[8];   const float* bq  = (const float*)d_in[9];
    const float* Wk  = (const float*)d_in[10];  const float* bk  = (const float*)d_in[11];
    const float* Wv  = (const float*)d_in[12];  const float* bv  = (const float*)d_in[13];
    const float* Wo  = (const float*)d_in[14];  const float* bo  = (const float*)d_in[15];
    const float* g1  = (const float*)d_in[16];  const float* b1  = (const float*)d_in[17];
    const float* g2  = (const float*)d_in[18];  const float* b2  = (const float*)d_in[19];
    const float* Wf1 = (const float*)d_in[20];  const float* bf1 = (const float*)d_in[21];
    const float* Wf2 = (const float*)d_in[22];  const float* bf2 = (const float*)d_in[23];
    float* out = (float*)d_out;

    float  *qp, *kp, *vp, *op, *ln1p, *f2p;
    __half *hA, *hB, *hip, *hpp, *hpt, *qh, *kh, *vt, *hat, *hln, *hff, *wh;
    cudaGetSymbolAddress((void**)&qp,  g_qp);
    cudaGetSymbolAddress((void**)&kp,  g_kp);
    cudaGetSymbolAddress((void**)&vp,  g_vp);
    cudaGetSymbolAddress((void**)&op,  g_o);
    cudaGetSymbolAddress((void**)&ln1p,g_ln1);
    cudaGetSymbolAddress((void**)&f2p, g_f2);
    cudaGetSymbolAddress((void**)&hA,  g_hA);
    cudaGetSymbolAddress((void**)&hB,  g_hB);
    cudaGetSymbolAddress((void**)&hip, g_hip);
    cudaGetSymbolAddress((void**)&hpp, g_hpp);
    cudaGetSymbolAddress((void**)&hpt, g_hpt);
    cudaGetSymbolAddress((void**)&qh,  g_qh);
    cudaGetSymbolAddress((void**)&kh,  g_kh);
    cudaGetSymbolAddress((void**)&vt,  g_vt);
    cudaGetSymbolAddress((void**)&hat, g_hat);
    cudaGetSymbolAddress((void**)&hln, g_hln);
    cudaGetSymbolAddress((void**)&hff, g_hff);
    cudaGetSymbolAddress((void**)&wh,  g_wh);

    __half* WipT = wh + 0*WSZ;
    __half* WppT = wh + 1*WSZ;
    __half* WqT  = wh + 2*WSZ;
    __half* WkT  = wh + 3*WSZ;
    __half* WvT  = wh + 4*WSZ;
    __half* WoT  = wh + 5*WSZ;
    __half* Wf1T = wh + 6*WSZ;
    __half* Wf2T = wh + 6*WSZ + WFSZ;

    cudaFuncSetAttribute(hgemm<0>,  cudaFuncAttributeMaxDynamicSharedMemorySize, HG_SMEM);
    cudaFuncSetAttribute(hgemm<1>,  cudaFuncAttributeMaxDynamicSharedMemorySize, HG_SMEM);
    cudaFuncSetAttribute(hgemm<9>,  cudaFuncAttributeMaxDynamicSharedMemorySize, HG_SMEM);
    cudaFuncSetAttribute(hgemm<10>, cudaFuncAttributeMaxDynamicSharedMemorySize, HG_SMEM);
    cudaFuncSetAttribute(attn_kernel, cudaFuncAttributeMaxDynamicSharedMemorySize, ATT_SMEM);

    // prep
    WPtrs P;
    P.s[0]=Wip; P.s[1]=Wpp; P.s[2]=Wq; P.s[3]=Wk; P.s[4]=Wv; P.s[5]=Wo; P.s[6]=Wf1; P.s[7]=Wf2;
    twr_all<<<dim3(48, 48, 8), dim3(32, 8)>>>(P, wh);
    cvt3<<<(MQ*EMBED/4 + 255)/256, 256>>>(image_pos, point_pos, point_tokens, hip, hpp, hpt);

    // positional projections + residual -> fp16
    hgemm<9><<<dim3(EMBED/128, MQ/128), 256, HG_SMEM>>>(hip, WipT, bip, image_tokens, hA, MQ, EMBED, EMBED);
    hgemm<9><<<dim3(EMBED/128, MK/128), 256, HG_SMEM>>>(hpp, WppT, bpp, point_tokens, hB, MK, EMBED, EMBED);
    // q, k, v projections -> fp32
    hgemm<0><<<dim3(EMBED/128, MQ/128), 256, HG_SMEM>>>(hA, WqT, bq, nullptr, qp, MQ, EMBED, EMBED);
    hgemm<0><<<dim3(EMBED/128, MK/128), 256, HG_SMEM>>>(hB, WkT, bk, nullptr, kp, MK, EMBED, EMBED);
    hgemm<0><<<dim3(EMBED/128, MK/128), 256, HG_SMEM>>>(hpt, WvT, bv, nullptr, vp, MK, EMBED, EMBED);
    // l2 normalize -> fp16; V transpose -> fp16
    l2norm_kernel<<<(MQ*HEADS)/8, 256>>>(qp, qh, MQ*HEADS);
    l2norm_kernel<<<(MK*HEADS)/8, 256>>>(kp, kh, MK*HEADS);
    vtrans_kernel<<<dim3(LK/32, EMBED/32, BATCH), dim3(32, 8)>>>(vp, vt);
    // attention -> fp16
    attn_kernel<<<dim3(LQ/64, HEADS, BATCH), 128, ATT_SMEM>>>(qh, kh, vt, hat);
    // output projection + residual -> fp32, LN1 (dual out)
    hgemm<1><<<dim3(EMBED/128, MQ/128), 256, HG_SMEM>>>(hat, WoT, bo, image_tokens, op, MQ, EMBED, EMBED);
    layernorm_kernel<true><<<MQ, 256>>>(op, g1, b1, ln1p, hln);
    // FFN
    hgemm<10><<<dim3(FF/128, MQ/128), 256, HG_SMEM>>>(hln, Wf1T, bf1, nullptr, hff, MQ, FF, EMBED);
    hgemm<1><<<dim3(EMBED/128, MQ/128), 256, HG_SMEM>>>(hff, Wf2T, bf2, ln1p, f2p, MQ, EMBED, FF);
    layernorm_kernel<false><<<MQ, 256>>>(f2p, g2, b2, out, nullptr);
}

// round 7
// speedup vs baseline: 6.6991x; 1.1893x over previous
#include <cuda_runtime.h>
#include <cuda_fp16.h>
#include <math.h>
#include <stdint.h>

#define EMBED 768
#define HEADS 12
#define HDIM  64
#define FF    1536
#define BATCH 4
#define LQ    2048
#define LK    2048
#define MQ    (BATCH*LQ)   /* 8192 */
#define MK    (BATCH*LK)   /* 8192 */
#define WSZ   (EMBED*EMBED)
#define WFSZ  (EMBED*FF)

// ---------------- scratch (no allocations allowed) ----------------
__device__ float  g_qp [MQ*EMBED];
__device__ float  g_kp [MK*EMBED];
__device__ float  g_vp [MK*EMBED];
__device__ float  g_o  [MQ*EMBED];
__device__ float  g_ln1[MQ*EMBED];
__device__ float  g_f2 [MQ*EMBED];
__device__ __half g_hA [MQ*EMBED];
__device__ __half g_hB [MK*EMBED];
__device__ __half g_hip[MQ*EMBED];
__device__ __half g_hpp[MK*EMBED];
__device__ __half g_hpt[MK*EMBED];
__device__ __half g_qh [MQ*EMBED];
__device__ __half g_kh [MK*EMBED];
__device__ __half g_vt [BATCH*EMBED*LK];
__device__ __half g_hat[MQ*EMBED];
__device__ __half g_hln[MQ*EMBED];
__device__ __half g_hff[MQ*FF];
__device__ __half g_wh [6*WSZ + 2*WFSZ];

// ---------------- helpers ----------------
__device__ __forceinline__ void cpasync16(void* s, const void* g) {
    uint32_t sa = (uint32_t)__cvta_generic_to_shared(s);
    asm volatile("cp.async.cg.shared.global [%0], [%1], 16;" :: "r"(sa), "l"(g));
}
#define CP_COMMIT() asm volatile("cp.async.commit_group;")

__device__ __forceinline__ uint32_t smem_u32(const void* p) {
    return (uint32_t)__cvta_generic_to_shared(p);
}

__device__ __forceinline__ void mma_f16(float c[4], const uint32_t a[4], const uint32_t b[2])
{
    asm volatile(
        "mma.sync.aligned.m16n8k16.row.col.f32.f16.f16.f32 "
        "{%0,%1,%2,%3}, {%4,%5,%6,%7}, {%8,%9}, {%0,%1,%2,%3};"
        : "+f"(c[0]), "+f"(c[1]), "+f"(c[2]), "+f"(c[3])
        : "r"(a[0]), "r"(a[1]), "r"(a[2]), "r"(a[3]), "r"(b[0]), "r"(b[1]));
}

__device__ __forceinline__ void ldsm_x4(uint32_t r[4], uint32_t addr) {
    asm volatile("ldmatrix.sync.aligned.m8n8.x4.shared.b16 {%0,%1,%2,%3}, [%4];"
        : "=r"(r[0]), "=r"(r[1]), "=r"(r[2]), "=r"(r[3]) : "r"(addr));
}

// ---------------- prep: fp16 copies of the three A-side inputs ----------------
__global__ void cvt3(const float* __restrict__ a, const float* __restrict__ b,
                     const float* __restrict__ c, __half* __restrict__ ha,
                     __half* __restrict__ hb, __half* __restrict__ hc)
{
    size_t i = ((size_t)blockIdx.x * 256 + threadIdx.x) * 4;
    if (i >= (size_t)MQ*EMBED) return;
    float4 va = *(const float4*)(a + i);
    float4 vb = *(const float4*)(b + i);
    float4 vc = *(const float4*)(c + i);
    *(__half2*)(ha + i)     = __floats2half2_rn(va.x, va.y);
    *(__half2*)(ha + i + 2) = __floats2half2_rn(va.z, va.w);
    *(__half2*)(hb + i)     = __floats2half2_rn(vb.x, vb.y);
    *(__half2*)(hb + i + 2) = __floats2half2_rn(vb.z, vb.w);
    *(__half2*)(hc + i)     = __floats2half2_rn(vc.x, vc.y);
    *(__half2*)(hc + i + 2) = __floats2half2_rn(vc.z, vc.w);
}

// ---------------- weight transpose + fp16 convert ----------------
struct WPtrs { const float* s[8]; };

__global__ void twr_all(WPtrs P, __half* __restrict__ wh)
{
    const int z = blockIdx.z;
    const int K = (z == 7) ? FF : EMBED;
    const int N = (z == 6) ? FF : EMBED;
    const int n0 = blockIdx.x * 32, k0 = blockIdx.y * 32;
    if (n0 >= N || k0 >= K) return;
    const float* src = P.s[z];
    size_t off = (z <= 5) ? (size_t)z * WSZ : (z == 6 ? (size_t)6*WSZ : (size_t)6*WSZ + WFSZ);
    __half* dst = wh + off;

    __shared__ float t[32][33];
    #pragma unroll
    for (int i = 0; i < 32; i += 8)
        t[threadIdx.y + i][threadIdx.x] =
            src[(size_t)(k0 + threadIdx.y + i) * N + n0 + threadIdx.x];
    __syncthreads();
    #pragma unroll
    for (int i = 0; i < 32; i += 8)
        dst[(size_t)(n0 + threadIdx.y + i) * K + k0 + threadIdx.x] =
            __float2half(t[threadIdx.x][threadIdx.y + i]);
}

// ---------------- fp16 GEMM 128x128x32, ldmatrix + 3-stage cp.async ----------------
#define HG_SMEM (3 * 20480)

template<int EPI>
__global__ __launch_bounds__(256)
void hgemm(const __half* __restrict__ A, const __half* __restrict__ Wt,
           const float* __restrict__ bias, const float* __restrict__ R,
           void* __restrict__ Cv, int M, int N, int K)
{
    extern __shared__ char smem[];

    const int tid  = threadIdx.x;
    const int lane = tid & 31;
    const int warp = tid >> 5;
    const int wm   = warp & 3;
    const int wn   = warp >> 2;
    const int bm   = blockIdx.y * 128;
    const int bn   = blockIdx.x * 128;
    const int NT   = K / 32;

    float acc[2][8][4];
    #pragma unroll
    for (int mi = 0; mi < 2; mi++)
        #pragma unroll
        for (int ni = 0; ni < 8; ni++)
            #pragma unroll
            for (int t = 0; t < 4; t++) acc[mi][ni][t] = 0.f;

    const int lr = tid >> 2;
    const int lc = tid & 3;

    const int g  = lane >> 3;
    const int ri = lane & 7;
    const int rowA_off = (wm*32 + (g & 1)*8 + ri) * 80 + (g >> 1)*16;
    const int rowB_off = 10240 + (wn*64 + (g >> 1)*8 + ri) * 80 + (g & 1)*16;

    #define HG_PREFETCH(s)  do {                                                     \
        char* _b = smem + ((s) % 3) * 20480;                                         \
        const int _k0 = (s) * 32;                                                    \
        _Pragma("unroll")                                                            \
        for (int _i = 0; _i < 2; _i++) {                                             \
            int _r = lr + 64*_i;                                                     \
            cpasync16(_b + _r*80 + lc*16,         A  + (size_t)(bm + _r) * K + _k0 + lc*8); \
            cpasync16(_b + 10240 + _r*80 + lc*16, Wt + (size_t)(bn + _r) * K + _k0 + lc*8); \
        }                                                                            \
        CP_COMMIT();                                                                 \
    } while (0)

    HG_PREFETCH(0);
    HG_PREFETCH(1);

    for (int s = 0; s < NT; s++) {
        asm volatile("cp.async.wait_group 1;");
        __syncthreads();
        if (s + 2 < NT) HG_PREFETCH(s + 2);

        const uint32_t buf = smem_u32(smem + (s % 3) * 20480);

        #pragma unroll
        for (int kk = 0; kk < 2; kk++) {
            uint32_t a[2][4];
            #pragma unroll
            for (int mi = 0; mi < 2; mi++)
                ldsm_x4(a[mi], buf + rowA_off + mi*16*80 + kk*32);
            uint32_t b[4][4];
            #pragma unroll
            for (int p = 0; p < 4; p++)
                ldsm_x4(b[p], buf + rowB_off + p*16*80 + kk*32);
            #pragma unroll
            for (int mi = 0; mi < 2; mi++)
                #pragma unroll
                for (int ni = 0; ni < 8; ni++)
                    mma_f16(acc[mi][ni], a[mi], &b[ni >> 1][(ni & 1)*2]);
        }
    }
    #undef HG_PREFETCH

    // epilogue
    #pragma unroll
    for (int mi = 0; mi < 2; mi++) {
        const int r0 = bm + wm*32 + mi*16 + (lane>>2);
        #pragma unroll
        for (int ni = 0; ni < 8; ni++) {
            const int c = bn + wn*64 + ni*8 + 2*(lane & 3);
            const float2 bb = *(const float2*)(bias + c);
            #pragma unroll
            for (int half_ = 0; half_ < 2; half_++) {
                const int r = r0 + half_*8;
                float v0 = acc[mi][ni][2*half_+0] + bb.x;
                float v1 = acc[mi][ni][2*half_+1] + bb.y;
                if (EPI & 1) {
                    const float2 rr = *(const float2*)(R + (size_t)r * N + c);
                    v0 += rr.x; v1 += rr.y;
                }
                if (EPI & 2) {
                    v0 = 0.5f * v0 * (1.f + erff(v0 * 0.70710678118654752f));
                    v1 = 0.5f * v1 * (1.f + erff(v1 * 0.70710678118654752f));
                }
                if (EPI & 8)
                    *(__half2*)((__half*)Cv + (size_t)r * N + c) = __floats2half2_rn(v0, v1);
                else
                    *(float2*)((float*)Cv + (size_t)r * N + c) = make_float2(v0, v1);
            }
        }
    }
}

// ---------------- per-head L2 normalize: fp32 in -> fp16 out ----------------
__global__ void l2norm_kernel(const float* __restrict__ x, __half* __restrict__ y, int nvec)
{
    const int warp = (blockIdx.x * blockDim.x + threadIdx.x) >> 5;
    const int lane = threadIdx.x & 31;
    if (warp >= nvec) return;
    const float* p = x + (size_t)warp * HDIM;
    float a = p[lane], b = p[lane + 32];
    float ss = a*a + b*b;
    #pragma unroll
    for (int m = 16; m; m >>= 1) ss += __shfl_xor_sync(0xffffffffu, ss, m);
    float n   = sqrtf(ss);
    float inv = 1.f / fmaxf(n, 1e-12f);
    __half* q = y + (size_t)warp * HDIM;
    q[lane]      = __float2half(a * inv);
    q[lane + 32] = __float2half(b * inv);
}

// ---------------- V transpose: vp fp32 [b*Lk+t][E] -> vt fp16 [b, E][Lk] ----------------
__global__ void vtrans_kernel(const float* __restrict__ vp, __half* __restrict__ vt)
{
    const int t0 = blockIdx.x * 32;
    const int d0 = blockIdx.y * 32;
    const int b  = blockIdx.z;
    __shared__ float t[32][33];
    #pragma unroll
    for (int i = 0; i < 32; i += 8)
        t[threadIdx.y + i][threadIdx.x] =
            vp[(size_t)(b*LK + t0 + threadIdx.y + i) * EMBED + d0 + threadIdx.x];
    __syncthreads();
    #pragma unroll
    for (int i = 0; i < 32; i += 8)
        vt[(size_t)(b*EMBED + d0 + threadIdx.y + i) * LK + t0 + threadIdx.x] =
            __float2half(t[threadIdx.x][threadIdx.y + i]);
}

// ---------------- LayerNorm over 768 ----------------
template<bool DUAL>
__global__ void layernorm_kernel(const float* __restrict__ x,
                                 const float* __restrict__ g,
                                 const float* __restrict__ b,
                                 float* __restrict__ y, __half* __restrict__ yh)
{
    const int row = blockIdx.x;
    const float* xr = x + (size_t)row * EMBED;
    const int tid = threadIdx.x;

    float v0 = xr[tid], v1 = xr[tid + 256], v2 = xr[tid + 512];

    __shared__ float red[8];
    float s = v0 + v1 + v2;
    #pragma unroll
    for (int m = 16; m; m >>= 1) s += __shfl_xor_sync(0xffffffffu, s, m);
    if ((tid & 31) == 0) red[tid >> 5] = s;
    __syncthreads();
    s = 0.f;
    #pragma unroll
    for (int w = 0; w < 8; w++) s += red[w];
    const float mu = s * (1.f / EMBED);
    __syncthreads();

    float d0 = v0 - mu, d1 = v1 - mu, d2 = v2 - mu;
    float ss = d0*d0 + d1*d1 + d2*d2;
    #pragma unroll
    for (int m = 16; m; m >>= 1) ss += __shfl_xor_sync(0xffffffffu, ss, m);
    if ((tid & 31) == 0) red[tid >> 5] = ss;
    __syncthreads();
    ss = 0.f;
    #pragma unroll
    for (int w = 0; w < 8; w++) ss += red[w];
    const float inv = rsqrtf(ss * (1.f / EMBED) + 1e-5f);

    float o0 = d0 * inv * g[tid]       + b[tid];
    float o1 = d1 * inv * g[tid + 256] + b[tid + 256];
    float o2 = d2 * inv * g[tid + 512] + b[tid + 512];
    float* yr = y + (size_t)row * EMBED;
    yr[tid] = o0; yr[tid + 256] = o1; yr[tid + 512] = o2;
    if (DUAL) {
        __half* hr = yh + (size_t)row * EMBED;
        hr[tid] = __float2half(o0);
        hr[tid + 256] = __float2half(o1);
        hr[tid + 512] = __float2half(o2);
    }
}

// ---------------- fp16 flash attention, ldmatrix frags ----------------
// scale-free: q,k unit vectors -> s in [-1,1] -> p = exp(s-1), no online max.
// 128 thr / 4 warps, q-tile 64 (16 rows/warp), kv-tile 64 double-buffered.
// smem halves, row stride 72 (144 B -> conflict-free ldsm across 8 rows)
#define ATT_SMEM (7 * 64 * 72 * 2)

__global__ __launch_bounds__(128)
void attn_kernel(const __half* __restrict__ q, const __half* __restrict__ k,
                 const __half* __restrict__ vt, __half* __restrict__ out)
{
    extern __shared__ __half hsm[];
    __half* Qs    = hsm;
    __half* Ks[2] = { Qs + 64*72,      Qs + 2*64*72 };
    __half* Vs[2] = { Qs + 3*64*72,    Qs + 4*64*72 };
    __half* Ps    = Qs + 5*64*72;

    const int tid  = threadIdx.x;
    const int lane = tid & 31;
    const int warp = tid >> 5;
    const int q0 = blockIdx.x * 64;
    const int h  = blockIdx.y;
    const int b  = blockIdx.z;

    const __half* qb  = q  + ((size_t)(b*LQ + q0)) * EMBED + h * HDIM;
    const __half* kb  = k  + ((size_t)(b*LK))      * EMBED + h * HDIM;
    const __half* vtb = vt + ((size_t)(b*EMBED + h*HDIM)) * LK;

    const int rl = tid >> 3;
    const int cl = (tid & 7) * 8;

    #pragma unroll
    for (int i = 0; i < 4; i++) {
        int r = rl + 16*i;
        cpasync16(Qs + r*72 + cl, qb + (size_t)r * EMBED + cl);
    }
    #pragma unroll
    for (int i = 0; i < 4; i++) {
        int r = rl + 16*i;
        cpasync16(Ks[0] + r*72 + cl, kb  + (size_t)r * EMBED + cl);
        cpasync16(Vs[0] + r*72 + cl, vtb + (size_t)r * LK + cl);
    }
    CP_COMMIT();

    float o[8][4];
    #pragma unroll
    for (int ni = 0; ni < 8; ni++)
        #pragma unroll
        for (int t = 0; t < 4; t++) o[ni][t] = 0.f;
    float l0 = 0.f, l1 = 0.f;

    __half* Pw = Ps + warp*16*72;
    const int rql = lane >> 2;

    // ldmatrix per-lane offsets (bytes)
    const int g2 = lane >> 3, ri = lane & 7;
    const uint32_t aQoff = (uint32_t)((warp*16 + (g2 & 1)*8 + ri) * 144 + (g2 >> 1)*16);
    const uint32_t aPoff = (uint32_t)(((g2 & 1)*8 + ri) * 144 + (g2 >> 1)*16);
    const uint32_t bOff  = (uint32_t)(((g2 >> 1)*8 + ri) * 144 + (g2 & 1)*16);
    const uint32_t qA  = smem_u32(Qs) + aQoff;
    const uint32_t pA  = smem_u32(Pw) + aPoff;

    for (int kt = 0; kt < LK/64; kt++) {
        asm volatile("cp.async.wait_group 0;");
        __syncthreads();

        const uint32_t kB = smem_u32(Ks[kt & 1]) + bOff;
        const uint32_t vB = smem_u32(Vs[kt & 1]) + bOff;

        if (kt + 1 < LK/64) {
            __half* ksn = Ks[(kt+1) & 1];
            __half* vsn = Vs[(kt+1) & 1];
            const __half* kp = kb  + (size_t)(kt+1) * 64 * EMBED;
            const __half* vp = vtb + (size_t)(kt+1) * 64;
            #pragma unroll
            for (int i = 0; i < 4; i++) {
                int r = rl + 16*i;
                cpasync16(ksn + r*72 + cl, kp + (size_t)r * EMBED + cl);
                cpasync16(vsn + r*72 + cl, vp + (size_t)r * LK + cl);
            }
            CP_COMMIT();
        }

        // S = Q @ K^T  (16 q-rows x 64 keys per warp, k = HDIM 64)
        float s[8][4];
        #pragma unroll
        for (int ni = 0; ni < 8; ni++)
            #pragma unroll
            for (int t = 0; t < 4; t++) s[ni][t] = 0.f;

        #pragma unroll
        for (int kk = 0; kk < 4; kk++) {
            uint32_t a[4];
            ldsm_x4(a, qA + kk*32);
            uint32_t bf[4][4];
            #pragma unroll
            for (int p = 0; p < 4; p++)
                ldsm_x4(bf[p], kB + p*16*144 + kk*32);
            #pragma unroll
            for (int ni = 0; ni < 8; ni++)
                mma_f16(s[ni], a, &bf[ni >> 1][(ni & 1)*2]);
        }

        // p = exp(s - 1); row sums; store fp16 P
        #pragma unroll
        for (int ni = 0; ni < 8; ni++) {
            float p0 = __expf(s[ni][0] - 1.f);
            float p1 = __expf(s[ni][1] - 1.f);
            float p2 = __expf(s[ni][2] - 1.f);
            float p3 = __expf(s[ni][3] - 1.f);
            l0 += p0 + p1;
            l1 += p2 + p3;
            __half* pp = Pw + rql*72 + ni*8 + 2*(lane & 3);
            *(__half2*)pp          = __floats2half2_rn(p0, p1);
            *(__half2*)(pp + 8*72) = __floats2half2_rn(p2, p3);
        }
        __syncwarp();

        // O += P @ V  (A = P [16 q][64 keys], B = Vt [d][key], k = keys)
        #pragma unroll
        for (int kk = 0; kk < 4; kk++) {
            uint32_t a[4];
            ldsm_x4(a, pA + kk*32);
            uint32_t bf[4][4];
            #pragma unroll
            for (int p = 0; p < 4; p++)
                ldsm_x4(bf[p], vB + p*16*144 + kk*32);
            #pragma unroll
            for (int ni = 0; ni < 8; ni++)
                mma_f16(o[ni], a, &bf[ni >> 1][(ni & 1)*2]);
        }
    }

    l0 += __shfl_xor_sync(0xffffffffu, l0, 1);
    l0 += __shfl_xor_sync(0xffffffffu, l0, 2);
    l1 += __shfl_xor_sync(0xffffffffu, l1, 1);
    l1 += __shfl_xor_sync(0xffffffffu, l1, 2);
    const float inv0 = 1.f / l0, inv1 = 1.f / l1;

    const int r = b*LQ + q0 + warp*16 + rql;
    #pragma unroll
    for (int ni = 0; ni < 8; ni++) {
        const int c = h*HDIM + ni*8 + 2*(lane & 3);
        *(__half2*)(out + (size_t)r * EMBED + c)     = __floats2half2_rn(o[ni][0]*inv0, o[ni][1]*inv0);
        *(__half2*)(out + (size_t)(r+8) * EMBED + c) = __floats2half2_rn(o[ni][2]*inv1, o[ni][3]*inv1);
    }
}

// ---------------- launch ----------------
extern "C" void kernel_launch(void* const* d_in, const int* in_sizes, int n_in,
                              void* d_out, int out_size)
{
    const float* image_tokens = (const float*)d_in[0];
    const float* point_tokens = (const float*)d_in[1];
    const float* image_pos    = (const float*)d_in[2];
    const float* point_pos    = (const float*)d_in[3];
    const float* Wip = (const float*)d_in[4];   const float* bip = (const float*)d_in[5];
    const float* Wpp = (const float*)d_in[6];   const float* bpp = (const float*)d_in[7];
    const float* Wq  = (const float*)d_in[8];   const float* bq  = (const float*)d_in[9];
    const float* Wk  = (const float*)d_in[10];  const float* bk  = (const float*)d_in[11];
    const float* Wv  = (const float*)d_in[12];  const float* bv  = (const float*)d_in[13];
    const float* Wo  = (const float*)d_in[14];  const float* bo  = (const float*)d_in[15];
    const float* g1  = (const float*)d_in[16];  const float* b1  = (const float*)d_in[17];
    const float* g2  = (const float*)d_in[18];  const float* b2  = (const float*)d_in[19];
    const float* Wf1 = (const float*)d_in[20];  const float* bf1 = (const float*)d_in[21];
    const float* Wf2 = (const float*)d_in[22];  const float* bf2 = (const float*)d_in[23];
    float* out = (float*)d_out;

    float  *qp, *kp, *vp, *op, *ln1p, *f2p;
    __half *hA, *hB, *hip, *hpp, *hpt, *qh, *kh, *vt, *hat, *hln, *hff, *wh;
    cudaGetSymbolAddress((void**)&qp,  g_qp);
    cudaGetSymbolAddress((void**)&kp,  g_kp);
    cudaGetSymbolAddress((void**)&vp,  g_vp);
    cudaGetSymbolAddress((void**)&op,  g_o);
    cudaGetSymbolAddress((void**)&ln1p,g_ln1);
    cudaGetSymbolAddress((void**)&f2p, g_f2);
    cudaGetSymbolAddress((void**)&hA,  g_hA);
    cudaGetSymbolAddress((void**)&hB,  g_hB);
    cudaGetSymbolAddress((void**)&hip, g_hip);
    cudaGetSymbolAddress((void**)&hpp, g_hpp);
    cudaGetSymbolAddress((void**)&hpt, g_hpt);
    cudaGetSymbolAddress((void**)&qh,  g_qh);
    cudaGetSymbolAddress((void**)&kh,  g_kh);
    cudaGetSymbolAddress((void**)&vt,  g_vt);
    cudaGetSymbolAddress((void**)&hat, g_hat);
    cudaGetSymbolAddress((void**)&hln, g_hln);
    cudaGetSymbolAddress((void**)&hff, g_hff);
    cudaGetSymbolAddress((void**)&wh,  g_wh);

    __half* WipT = wh + 0*WSZ;
    __half* WppT = wh + 1*WSZ;
    __half* WqT  = wh + 2*WSZ;
    __half* WkT  = wh + 3*WSZ;
    __half* WvT  = wh + 4*WSZ;
    __half* WoT  = wh + 5*WSZ;
    __half* Wf1T = wh + 6*WSZ;
    __half* Wf2T = wh + 6*WSZ + WFSZ;

    static cudaStream_t s1 = nullptr, s2 = nullptr;
    static cudaEvent_t evA = nullptr, evB = nullptr, evC = nullptr;
    if (!s1) {
        cudaStreamCreateWithFlags(&s1, cudaStreamNonBlocking);
        cudaStreamCreateWithFlags(&s2, cudaStreamNonBlocking);
        cudaEventCreateWithFlags(&evA, cudaEventDisableTiming);
        cudaEventCreateWithFlags(&evB, cudaEventDisableTiming);
        cudaEventCreateWithFlags(&evC, cudaEventDisableTiming);
    }

    cudaFuncSetAttribute(hgemm<0>,  cudaFuncAttributeMaxDynamicSharedMemorySize, HG_SMEM);
    cudaFuncSetAttribute(hgemm<1>,  cudaFuncAttributeMaxDynamicSharedMemorySize, HG_SMEM);
    cudaFuncSetAttribute(hgemm<9>,  cudaFuncAttributeMaxDynamicSharedMemorySize, HG_SMEM);
    cudaFuncSetAttribute(hgemm<10>, cudaFuncAttributeMaxDynamicSharedMemorySize, HG_SMEM);
    cudaFuncSetAttribute(attn_kernel, cudaFuncAttributeMaxDynamicSharedMemorySize, ATT_SMEM);

    // prep (stream 0)
    WPtrs P;
    P.s[0]=Wip; P.s[1]=Wpp; P.s[2]=Wq; P.s[3]=Wk; P.s[4]=Wv; P.s[5]=Wo; P.s[6]=Wf1; P.s[7]=Wf2;
    twr_all<<<dim3(48, 48, 8), dim3(32, 8)>>>(P, wh);
    cvt3<<<(MQ*EMBED/4 + 255)/256, 256>>>(image_pos, point_pos, point_tokens, hip, hpp, hpt);
    cudaEventRecord(evA, 0);

    // branch Q (stream 0): ip-proj -> q-proj -> l2norm q
    hgemm<9><<<dim3(EMBED/128, MQ/128), 256, HG_SMEM>>>(hip, WipT, bip, image_tokens, hA, MQ, EMBED, EMBED);
    hgemm<0><<<dim3(EMBED/128, MQ/128), 256, HG_SMEM>>>(hA, WqT, bq, nullptr, qp, MQ, EMBED, EMBED);
    l2norm_kernel<<<(MQ*HEADS)/8, 256>>>(qp, qh, MQ*HEADS);

    // branch K (stream s1): pp-proj -> k-proj -> l2norm k
    cudaStreamWaitEvent(s1, evA, 0);
    hgemm<9><<<dim3(EMBED/128, MK/128), 256, HG_SMEM, s1>>>(hpp, WppT, bpp, point_tokens, hB, MK, EMBED, EMBED);
    hgemm<0><<<dim3(EMBED/128, MK/128), 256, HG_SMEM, s1>>>(hB, WkT, bk, nullptr, kp, MK, EMBED, EMBED);
    l2norm_kernel<<<(MK*HEADS)/8, 256, 0, s1>>>(kp, kh, MK*HEADS);
    cudaEventRecord(evB, s1);

    // branch V (stream s2): v-proj -> vtrans
    cudaStreamWaitEvent(s2, evA, 0);
    hgemm<0><<<dim3(EMBED/128, MK/128), 256, HG_SMEM, s2>>>(hpt, WvT, bv, nullptr, vp, MK, EMBED, EMBED);
    vtrans_kernel<<<dim3(LK/32, EMBED/32, BATCH), dim3(32, 8), 0, s2>>>(vp, vt);
    cudaEventRecord(evC, s2);

    // join on stream 0
    cudaStreamWaitEvent(0, evB, 0);
    cudaStreamWaitEvent(0, evC, 0);

    // attention -> fp16
    attn_kernel<<<dim3(LQ/64, HEADS, BATCH), 128, ATT_SMEM>>>(qh, kh, vt, hat);
    // output projection + residual -> fp32, LN1 (dual out)
    hgemm<1><<<dim3(EMBED/128, MQ/128), 256, HG_SMEM>>>(hat, WoT, bo, image_tokens, op, MQ, EMBED, EMBED);
    layernorm_kernel<true><<<MQ, 256>>>(op, g1, b1, ln1p, hln);
    // FFN
    hgemm<10><<<dim3(FF/128, MQ/128), 256, HG_SMEM>>>(hln, Wf1T, bf1, nullptr, hff, MQ, FF, EMBED);
    hgemm<1><<<dim3(EMBED/128, MQ/128), 256, HG_SMEM>>>(hff, Wf2T, bf2, ln1p, f2p, MQ, EMBED, FF);
    layernorm_kernel<false><<<MQ, 256>>>(f2p, g2, b2, out, nullptr);
}